// round 12
// baseline (speedup 1.0000x reference)
#include <cuda_runtime.h>
#include <cuda_fp16.h>
#include <stdint.h>

#define NB  16
#define SLQ 2048
#define SLK 2048
#define SDQ 768
#define SDK 1024
#define LOG2E 1.4426950408889634f

// ---------------------------------------------------------------------------
// Device-global scratch
// ---------------------------------------------------------------------------
__device__ __half g_qh  [(size_t)NB*SLQ*SDQ];   // fp16(query)
__device__ __half g_kh  [(size_t)NB*SLK*SDK];   // fp16(key)
__device__ __half g_wq16[SDQ*SDK];              // fp16(Wq)   [768,1024]
__device__ __half g_wk16[SDK*SDK];              // fp16(Wk)   [1024,1024]
__device__ __half g_wvt [SDK*SDK];              // fp16(Wv^T) [1024,1024]
__device__ __half g_M2  [SDQ*SDK];              // Wq@Wk^T    [768,1024]
__device__ __half g_Kred[(size_t)NB*SLK*SDQ];   // key@M2^T   [B*Lk,768]
__device__ __half g_Vth [(size_t)NB*SDK*SLK];   // V^T        [B,Dk,Lk]
__device__ __half g_Sf  [(size_t)NB*SLQ*SLK];   // exp(scores) fp16
__device__ float  g_part[(size_t)NB*SLQ*8];     // per-CTA partial row sums
__device__ float  g_w   [SDK];                  // Wk @ bq
__device__ float  g_cs  [NB*SLK];               // (key@w)/32 * log2e

// ---------------------------------------------------------------------------
// PTX helpers — baseline (non-'a') features only
// ---------------------------------------------------------------------------
__device__ __forceinline__ uint32_t smem_u32(const void* p) {
    uint32_t a;
    asm("{ .reg .u64 t; cvta.to.shared.u64 t, %1; cvt.u32.u64 %0, t; }"
        : "=r"(a) : "l"(p));
    return a;
}
__device__ __forceinline__ void cpa16(uint32_t dst, const void* src) {
    asm volatile("cp.async.cg.shared.global [%0], [%1], 16;"
                 :: "r"(dst), "l"(src) : "memory");
}
__device__ __forceinline__ void cpa_commit() {
    asm volatile("cp.async.commit_group;" ::: "memory");
}
template<int N>
__device__ __forceinline__ void cpa_wait() {
    asm volatile("cp.async.wait_group %0;" :: "n"(N) : "memory");
}
__device__ __forceinline__ void ldmx4(uint32_t* r, uint32_t addr) {
    asm volatile("ldmatrix.sync.aligned.m8n8.x4.shared.b16 {%0,%1,%2,%3}, [%4];"
                 : "=r"(r[0]), "=r"(r[1]), "=r"(r[2]), "=r"(r[3]) : "r"(addr));
}
__device__ __forceinline__ void mma16816(float* c, const uint32_t* a, const uint32_t* b) {
    asm volatile(
        "mma.sync.aligned.m16n8k16.row.col.f32.f16.f16.f32 "
        "{%0,%1,%2,%3}, {%4,%5,%6,%7}, {%8,%9}, {%0,%1,%2,%3};"
        : "+f"(c[0]), "+f"(c[1]), "+f"(c[2]), "+f"(c[3])
        : "r"(a[0]), "r"(a[1]), "r"(a[2]), "r"(a[3]), "r"(b[0]), "r"(b[1]));
}
__device__ __forceinline__ uint32_t sw128(uint32_t o) { return o ^ ((o >> 3) & 0x70); }

__device__ __forceinline__ uint32_t hpack(float x, float y) {
    __half hx = __float2half_rn(x), hy = __float2half_rn(y);
    return (uint32_t)__half_as_ushort(hx) | ((uint32_t)__half_as_ushort(hy) << 16);
}
__device__ __forceinline__ float ex2(float x) {
    float y;
    asm("ex2.approx.f32 %0, %1;" : "=f"(y) : "f"(x));
    return y;
}

// ---------------------------------------------------------------------------
// fp16 single-pass HMMA GEMM:  D[M,N] = alpha * (A @ B^T) (+ bias / scale)
//   A [M,K] K-major fp16; B [N,K] K-major fp16.
//   CTA 128x256, BK=64 (SW128), 4-stage cp.async (one sync/iter), 8 warps,
//   warp tile 64x64, mma.m16n8k16.
// OUTMODE: 0 = fp32; 2 = fp16;
//          3 = fp16 exp2(v) + deterministic per-CTA row-sum partials in Cf
// BIASMODE: 0 = none; 1 = per column (fp32, batched); 2 = per row;
//           4 = per-row scale = 1/sum(8 fp32 partials) (batched)
// ---------------------------------------------------------------------------
#define BM 128
#define BN 256
#define BKC 64
#define OFF_B  16384u
#define STAGE  49152u
#define NSTG   4
#define GEMM_SMEM (NSTG * 49152)     // 196608

template<int OUTMODE, int BIASMODE>
__global__ void __launch_bounds__(256, 1) mma_gemm(
    const __half* __restrict__ Ah, const __half* __restrict__ Bh,
    const float* __restrict__ bias,
    float* __restrict__ Cf, __half* __restrict__ Chi,
    int N, int K, float alpha,
    long batchA, long batchB, long batchC, long biasBatch)
{
    extern __shared__ char smem[];
    const uint32_t sbase = smem_u32(smem);
    const int tid  = threadIdx.x;
    const int lane = tid & 31;
    const int wid  = tid >> 5;
    const int wm   = wid >> 2;   // 0..1  (m64)
    const int wn   = wid & 3;    // 0..3  (n64)
    const int row0 = blockIdx.y * BM;
    const int col0 = blockIdx.x * BN;
    const size_t zA = (size_t)blockIdx.z * batchA;
    const size_t zB = (size_t)blockIdx.z * batchB;
    const size_t zC = (size_t)blockIdx.z * batchC;
    const float* bp = bias ? bias + (size_t)blockIdx.z * biasBatch : bias;

    const int r8 = tid >> 3;              // 0..31
    const uint32_t cb = (tid & 7) * 16;   // byte offset within 128B row

    // Hoisted loader invariants: swizzled smem offsets + global row bases.
    uint32_t soA[4], soB[8];
    const char *pA[4], *pB[8];
    #pragma unroll
    for (int i = 0; i < 4; i++) {
        int r = r8 + i * 32;
        soA[i] = sw128((uint32_t)(r * 128) + cb);
        pA[i]  = (const char*)(Ah + zA + (size_t)(row0 + r) * K) + cb;
    }
    #pragma unroll
    for (int i = 0; i < 8; i++) {
        int r = r8 + i * 32;
        soB[i] = sw128((uint32_t)(r * 128) + cb);
        pB[i]  = (const char*)(Bh + zB + (size_t)(col0 + r) * K) + cb;
    }

    auto load_stage = [&](int s, int k0) {
        const uint32_t st = sbase + s * STAGE;
        const size_t kb = (size_t)k0 * 2;          // bytes along K
        #pragma unroll
        for (int i = 0; i < 4; i++)
            cpa16(st + soA[i], pA[i] + kb);
        #pragma unroll
        for (int i = 0; i < 8; i++)
            cpa16(st + OFF_B + soB[i], pB[i] + kb);
        cpa_commit();
    };

    float c[4][8][4];
    #pragma unroll
    for (int i = 0; i < 4; i++)
        #pragma unroll
        for (int j = 0; j < 8; j++)
            #pragma unroll
            for (int k = 0; k < 4; k++) c[i][j][k] = 0.f;

    const int nk = K / BKC;                // >= 12 for all our shapes
    load_stage(0, 0);
    load_stage(1, BKC);
    load_stage(2, 2 * BKC);

    const int a_r = ((lane >> 3) & 1) * 8 + (lane & 7);
    const int a_k = ((lane >> 4) & 1) * 16;
    const int b_r = ((lane >> 4) & 1) * 8 + (lane & 7);
    const int b_k = ((lane >> 3) & 1) * 16;

    for (int i = 0; i < nk; i++) {
        // ensure cp.async group i has completed
        if (i + 3 <= nk)      cpa_wait<2>();
        else if (i + 2 == nk) cpa_wait<1>();
        else                  cpa_wait<0>();
        __syncthreads();                  // stage i%4 ready; (i-1)%4 freed
        if (i + 3 < nk) load_stage((i + 3) % NSTG, (i + 3) * BKC);

        const uint32_t st = sbase + (i % NSTG) * STAGE;
        #pragma unroll
        for (int ks = 0; ks < 4; ks++) {
            uint32_t a_[4][4];
            #pragma unroll
            for (int fm = 0; fm < 4; fm++) {
                int row = wm * 64 + fm * 16 + a_r;
                uint32_t so = sw128((uint32_t)(row * 128) + ks * 32 + a_k);
                ldmx4(a_[fm], st + so);
            }
            uint32_t b_[4][4];
            #pragma unroll
            for (int g = 0; g < 4; g++) {
                int row = wn * 64 + g * 16 + b_r;
                uint32_t so = sw128((uint32_t)(row * 128) + ks * 32 + b_k);
                ldmx4(b_[g], st + OFF_B + so);
            }
            #pragma unroll
            for (int fm = 0; fm < 4; fm++)
                #pragma unroll
                for (int fn = 0; fn < 8; fn++)
                    mma16816(c[fm][fn], a_[fm], &b_[fn >> 1][(fn & 1) * 2]);
        }
    }

    // ---- epilogue -------------------------------------------------------
    float rsum[8];
    if (OUTMODE == 3) {
        #pragma unroll
        for (int r = 0; r < 8; r++) rsum[r] = 0.f;
    }

    #pragma unroll
    for (int fm = 0; fm < 4; fm++) {
        int rowb = row0 + wm * 64 + fm * 16 + (lane >> 2);
        float rs0 = 1.f, rs1 = 1.f;
        if (BIASMODE == 2) { rs0 = bp[rowb]; rs1 = bp[rowb + 8]; }
        if (BIASMODE == 4) {
            const float* p0 = bp + (size_t)rowb * 8;
            const float* p1 = bp + (size_t)(rowb + 8) * 8;
            float s0 = ((p0[0]+p0[1])+(p0[2]+p0[3])) + ((p0[4]+p0[5])+(p0[6]+p0[7]));
            float s1 = ((p1[0]+p1[1])+(p1[2]+p1[3])) + ((p1[4]+p1[5])+(p1[6]+p1[7]));
            rs0 = 1.f / s0; rs1 = 1.f / s1;
        }
        #pragma unroll
        for (int fn = 0; fn < 8; fn++) {
            int col = col0 + wn * 64 + fn * 8 + (lane & 3) * 2;
            float v0 = c[fm][fn][0] * alpha, v1 = c[fm][fn][1] * alpha;
            float v2 = c[fm][fn][2] * alpha, v3 = c[fm][fn][3] * alpha;
            if (BIASMODE == 1) {
                float b0 = bp[col], b1 = bp[col + 1];
                v0 += b0; v1 += b1; v2 += b0; v3 += b1;
            }
            if (BIASMODE == 2) {
                v0 += rs0; v1 += rs0; v2 += rs1; v3 += rs1;
            }
            if (BIASMODE == 4) {
                v0 *= rs0; v1 *= rs0; v2 *= rs1; v3 *= rs1;
            }
            size_t o0 = zC + (size_t)rowb * N + col;
            size_t o1 = o0 + (size_t)8 * N;
            if (OUTMODE == 0) {
                *(float2*)(Cf + o0) = make_float2(v0, v1);
                *(float2*)(Cf + o1) = make_float2(v2, v3);
            } else if (OUTMODE == 2) {
                *(uint32_t*)(Chi + o0) = hpack(v0, v1);
                *(uint32_t*)(Chi + o1) = hpack(v2, v3);
            } else {                                  // OUTMODE == 3
                float e0 = ex2(v0), e1 = ex2(v1);
                float e2 = ex2(v2), e3 = ex2(v3);
                *(uint32_t*)(Chi + o0) = hpack(e0, e1);
                *(uint32_t*)(Chi + o1) = hpack(e2, e3);
                rsum[fm * 2]     += e0 + e1;
                rsum[fm * 2 + 1] += e2 + e3;
            }
        }
    }

    if (OUTMODE == 3) {
        // deterministic row-sum reduction -> per-CTA partials
        #pragma unroll
        for (int r = 0; r < 8; r++) {
            rsum[r] += __shfl_xor_sync(0xffffffffu, rsum[r], 1);
            rsum[r] += __shfl_xor_sync(0xffffffffu, rsum[r], 2);
        }
        __syncthreads();                      // safe to reuse stage smem
        float* arr = (float*)smem;            // [4][128]
        if ((lane & 3) == 0) {
            #pragma unroll
            for (int fm = 0; fm < 4; fm++) {
                int r0 = wm * 64 + fm * 16 + (lane >> 2);
                arr[wn * 128 + r0]     = rsum[fm * 2];
                arr[wn * 128 + r0 + 8] = rsum[fm * 2 + 1];
            }
        }
        __syncthreads();
        if (tid < 128) {
            float s = (arr[tid] + arr[128 + tid]) + (arr[256 + tid] + arr[384 + tid]);
            size_t grow = (size_t)blockIdx.z * (gridDim.y * BM) + row0 + tid;
            Cf[grow * gridDim.x + blockIdx.x] = s;
        }
    }
}

// ---------------------------------------------------------------------------
// Merged convert: 4 segments of fp32 -> fp16.  All sizes multiples of 2048.
// ---------------------------------------------------------------------------
__global__ void __launch_bounds__(256) cvt4_kernel(
    const float* __restrict__ s0, __half* __restrict__ d0, unsigned B0,
    const float* __restrict__ s1, __half* __restrict__ d1, unsigned B1,
    const float* __restrict__ s2, __half* __restrict__ d2, unsigned B2,
    const float* __restrict__ s3, __half* __restrict__ d3)
{
    unsigned b = blockIdx.x;
    const float* s; __half* d;
    if (b < B0)                { s = s0; d = d0; }
    else if (b < B0 + B1)      { s = s1; d = d1; b -= B0; }
    else if (b < B0 + B1 + B2) { s = s2; d = d2; b -= B0 + B1; }
    else                       { s = s3; d = d3; b -= B0 + B1 + B2; }
    size_t i = ((size_t)b * 256 + threadIdx.x) * 8;
    float4 v0 = *(const float4*)(s + i);
    float4 v1 = *(const float4*)(s + i + 4);
    uint4 o;
    o.x = hpack(v0.x, v0.y);
    o.y = hpack(v0.z, v0.w);
    o.z = hpack(v1.x, v1.y);
    o.w = hpack(v1.z, v1.w);
    *(uint4*)(d + i) = o;
}

// ---------------------------------------------------------------------------
// Transposed convert: W [K,N] fp32 -> Wt [N,K] fp16   (Wv only)
// ---------------------------------------------------------------------------
__global__ void transpose_cvt_kernel(const float* __restrict__ W,
                                     __half* __restrict__ hi, int K, int N)
{
    __shared__ float t[32][33];
    int n0 = blockIdx.x * 32, k0 = blockIdx.y * 32;
    int x = threadIdx.x, y = threadIdx.y;
    #pragma unroll
    for (int j = 0; j < 32; j += 8)
        t[y + j][x] = W[(size_t)(k0 + y + j) * N + n0 + x];
    __syncthreads();
    #pragma unroll
    for (int j = 0; j < 32; j += 8)
        hi[(size_t)(n0 + y + j) * K + k0 + x] = __float2half_rn(t[x][y + j]);
}

// ---------------------------------------------------------------------------
// w = Wk @ bq  (fp32 exact).  One block per row.
// ---------------------------------------------------------------------------
__global__ void __launch_bounds__(256) wvec_kernel(
    const float* __restrict__ Wk, const float* __restrict__ bq,
    float* __restrict__ w)
{
    const int i = blockIdx.x;
    const int tid = threadIdx.x;
    float s = 0.f;
    #pragma unroll
    for (int j = 0; j < 4; j++) {
        int o = tid + j * 256;
        s += Wk[(size_t)i * SDK + o] * bq[o];
    }
    #pragma unroll
    for (int off = 16; off; off >>= 1)
        s += __shfl_xor_sync(0xffffffffu, s, off);
    __shared__ float red[8];
    if ((tid & 31) == 0) red[tid >> 5] = s;
    __syncthreads();
    if (tid == 0) {
        float t = 0.f;
        #pragma unroll
        for (int k = 0; k < 8; k++) t += red[k];
        w[i] = t;
    }
}

// ---------------------------------------------------------------------------
// cs[j] = dot(kh[j,:], w) * (log2e/32).  One WARP per key row, 8 rows/CTA.
// Coalesced: lane L reads 16B at row_byte_offset L*16 + pass*512.
// ---------------------------------------------------------------------------
__global__ void __launch_bounds__(256) cvec_kernel(
    const __half* __restrict__ kh, const float* __restrict__ w,
    float* __restrict__ cs)
{
    const int lane = threadIdx.x & 31;
    const size_t row = (size_t)blockIdx.x * 8 + (threadIdx.x >> 5);
    const uint4* kr = (const uint4*)(kh + row * SDK);
    float s = 0.f;
    #pragma unroll
    for (int t = 0; t < 4; t++) {
        uint4 v = kr[lane + t * 32];                 // 8 halves
        int e0 = (lane + t * 32) * 8;                // element base
        __half2 h0 = *(__half2*)&v.x, h1 = *(__half2*)&v.y;
        __half2 h2 = *(__half2*)&v.z, h3 = *(__half2*)&v.w;
        float2 f0 = __half22float2(h0), f1 = __half22float2(h1);
        float2 f2 = __half22float2(h2), f3 = __half22float2(h3);
        s += f0.x * w[e0]     + f0.y * w[e0 + 1]
           + f1.x * w[e0 + 2] + f1.y * w[e0 + 3]
           + f2.x * w[e0 + 4] + f2.y * w[e0 + 5]
           + f3.x * w[e0 + 6] + f3.y * w[e0 + 7];
    }
    #pragma unroll
    for (int off = 16; off; off >>= 1)
        s += __shfl_xor_sync(0xffffffffu, s, off);
    if (lane == 0) cs[row] = s * (0.03125f * LOG2E);
}

// ---------------------------------------------------------------------------
// kernel_launch
// ---------------------------------------------------------------------------
extern "C" void kernel_launch(void* const* d_in, const int* in_sizes, int n_in,
                              void* d_out, int out_size)
{
    const float* query = (const float*)d_in[0];
    const float* key   = (const float*)d_in[1];
    const float* Wq    = (const float*)d_in[2];
    const float* bq    = (const float*)d_in[3];
    const float* Wk    = (const float*)d_in[4];
    const float* bk    = (const float*)d_in[5];   // vanishes under softmax
    const float* Wv    = (const float*)d_in[6];
    const float* bv    = (const float*)d_in[7];
    float* out = (float*)d_out;
    (void)bk;

    __half *qh,*kh,*wq16,*wk16,*wvt,*M2,*Kred,*Vth,*Sf;
    float *w,*cs,*part;
    cudaGetSymbolAddress((void**)&qh,   g_qh);
    cudaGetSymbolAddress((void**)&kh,   g_kh);
    cudaGetSymbolAddress((void**)&wq16, g_wq16);
    cudaGetSymbolAddress((void**)&wk16, g_wk16);
    cudaGetSymbolAddress((void**)&wvt,  g_wvt);
    cudaGetSymbolAddress((void**)&M2,   g_M2);
    cudaGetSymbolAddress((void**)&Kred, g_Kred);
    cudaGetSymbolAddress((void**)&Vth,  g_Vth);
    cudaGetSymbolAddress((void**)&Sf,   g_Sf);
    cudaGetSymbolAddress((void**)&w,    g_w);
    cudaGetSymbolAddress((void**)&cs,   g_cs);
    cudaGetSymbolAddress((void**)&part, g_part);

    cudaFuncSetAttribute(mma_gemm<2,0>, cudaFuncAttributeMaxDynamicSharedMemorySize, GEMM_SMEM);
    cudaFuncSetAttribute(mma_gemm<2,2>, cudaFuncAttributeMaxDynamicSharedMemorySize, GEMM_SMEM);
    cudaFuncSetAttribute(mma_gemm<3,1>, cudaFuncAttributeMaxDynamicSharedMemorySize, GEMM_SMEM);
    cudaFuncSetAttribute(mma_gemm<0,4>, cudaFuncAttributeMaxDynamicSharedMemorySize, GEMM_SMEM);

    // 1. all fp32->fp16 converts in ONE launch (query, key, Wq, Wk)
    {
        const unsigned Bq  = (unsigned)((size_t)NB * SLQ * SDQ / 2048);  // 12288
        const unsigned Bk  = (unsigned)((size_t)NB * SLK * SDK / 2048);  // 16384
        const unsigned Bwq = (unsigned)((size_t)SDQ * SDK / 2048);       // 384
        const unsigned Bwk = (unsigned)((size_t)SDK * SDK / 2048);       // 512
        cvt4_kernel<<<Bq + Bk + Bwq + Bwk, 256>>>(
            query, qh, Bq, key, kh, Bk, Wq, wq16, Bwq, Wk, wk16);
    }
    transpose_cvt_kernel<<<dim3(SDK/32, SDK/32), dim3(32,8)>>>(Wv, wvt, SDK, SDK);

    // 2. bias column (log2-domain): w = Wk@bq ; cs = (kh@w) * log2e/32
    wvec_kernel<<<SDK, 256>>>(Wk, bq, w);
    cvec_kernel<<<NB*SLK/8, 256>>>(kh, w, cs);

    // 3. M2 = Wq @ Wk^T  (M=768, N=1024, K=1024) -> fp16
    mma_gemm<2,0><<<dim3(SDK/BN, SDQ/BM, 1), 256, GEMM_SMEM>>>(
        wq16, wk16, nullptr, nullptr, M2, SDK, SDK, 1.f, 0, 0, 0, 0);

    // 4. Kred = key @ M2^T  (M=32768, N=768, K=1024) -> fp16
    mma_gemm<2,0><<<dim3(SDQ/BN, (NB*SLK)/BM, 1), 256, GEMM_SMEM>>>(
        kh, M2, nullptr, nullptr, Kred, SDQ, SDK, 1.f, 0, 0, 0, 0);

    // 5. V projection, transposed out: Vt[b][d][t] (M=1024, N=2048, K=1024)
    mma_gemm<2,2><<<dim3(SLK/BN, SDK/BM, NB), 256, GEMM_SMEM>>>(
        wvt, kh, bv, nullptr, Vth,
        SLK, SDK, 1.f, 0, (long)SLK*SDK, (long)SDK*SLK, 0);

    // 6. Sf = exp2(query @ Kred^T * log2e/32 + cs), plus deterministic
    //    per-CTA row-sum partials
    mma_gemm<3,1><<<dim3(SLK/BN, SLQ/BM, NB), 256, GEMM_SMEM>>>(
        qh, Kred, cs, part, Sf,
        SLK, SDQ, 0.03125f * LOG2E,
        (long)SLQ*SDQ, (long)SLK*SDQ, (long)SLQ*SLK, SLK);

    // 7. out = (Sf @ Vt^T) * (1/rowsum from partials)  (M=2048, N=1024, K=2048)
    mma_gemm<0,4><<<dim3(SDK/BN, SLQ/BM, NB), 256, GEMM_SMEM>>>(
        Sf, Vth, part, out, nullptr,
        SDK, SLK, 1.f, (long)SLQ*SLK, (long)SDK*SLK, (long)SLQ*SDK, (long)SLQ*8);
}

// round 13
// speedup vs baseline: 1.0244x; 1.0244x over previous
#include <cuda_runtime.h>
#include <cuda_fp16.h>
#include <stdint.h>

#define NB  16
#define SLQ 2048
#define SLK 2048
#define SDQ 768
#define SDK 1024
#define LOG2E 1.4426950408889634f

// ---------------------------------------------------------------------------
// Device-global scratch
// ---------------------------------------------------------------------------
__device__ __half g_qh  [(size_t)NB*SLQ*SDQ];   // fp16(query)
__device__ __half g_kh  [(size_t)NB*SLK*SDK];   // fp16(key)
__device__ __half g_wq16[SDQ*SDK];              // fp16(Wq)   [768,1024]
__device__ __half g_wk16[SDK*SDK];              // fp16(Wk)   [1024,1024]
__device__ __half g_wvt [SDK*SDK];              // fp16(Wv^T) [1024,1024]
__device__ __half g_M2  [SDQ*SDK];              // Wq@Wk^T    [768,1024]
__device__ __half g_Kred[(size_t)NB*SLK*SDQ];   // key@M2^T   [B*Lk,768]
__device__ __half g_Vth [(size_t)NB*SDK*SLK];   // V^T        [B,Dk,Lk]
__device__ __half g_Sf  [(size_t)NB*SLQ*SLK];   // exp(scores) fp16
__device__ float  g_part[(size_t)NB*SLQ*8];     // per-CTA partial row sums
__device__ float  g_rs  [NB*SLQ];               // 1 / row sum
__device__ __half g_w16 [SDK];                  // fp16(Wk @ bq)
__device__ float  g_cs  [NB*SLK];               // (key@w)/32 * log2e

// ---------------------------------------------------------------------------
// PTX helpers — baseline (non-'a') features only
// ---------------------------------------------------------------------------
__device__ __forceinline__ uint32_t smem_u32(const void* p) {
    uint32_t a;
    asm("{ .reg .u64 t; cvta.to.shared.u64 t, %1; cvt.u32.u64 %0, t; }"
        : "=r"(a) : "l"(p));
    return a;
}
__device__ __forceinline__ void cpa16(uint32_t dst, const void* src) {
    asm volatile("cp.async.cg.shared.global [%0], [%1], 16;"
                 :: "r"(dst), "l"(src) : "memory");
}
__device__ __forceinline__ void cpa_commit() {
    asm volatile("cp.async.commit_group;" ::: "memory");
}
template<int N>
__device__ __forceinline__ void cpa_wait() {
    asm volatile("cp.async.wait_group %0;" :: "n"(N) : "memory");
}
__device__ __forceinline__ void ldmx4(uint32_t* r, uint32_t addr) {
    asm volatile("ldmatrix.sync.aligned.m8n8.x4.shared.b16 {%0,%1,%2,%3}, [%4];"
                 : "=r"(r[0]), "=r"(r[1]), "=r"(r[2]), "=r"(r[3]) : "r"(addr));
}
__device__ __forceinline__ void mma16816(float* c, const uint32_t* a, const uint32_t* b) {
    asm volatile(
        "mma.sync.aligned.m16n8k16.row.col.f32.f16.f16.f32 "
        "{%0,%1,%2,%3}, {%4,%5,%6,%7}, {%8,%9}, {%0,%1,%2,%3};"
        : "+f"(c[0]), "+f"(c[1]), "+f"(c[2]), "+f"(c[3])
        : "r"(a[0]), "r"(a[1]), "r"(a[2]), "r"(a[3]), "r"(b[0]), "r"(b[1]));
}
__device__ __forceinline__ uint32_t sw128(uint32_t o) { return o ^ ((o >> 3) & 0x70); }

__device__ __forceinline__ uint32_t hpack(float x, float y) {
    __half hx = __float2half_rn(x), hy = __float2half_rn(y);
    return (uint32_t)__half_as_ushort(hx) | ((uint32_t)__half_as_ushort(hy) << 16);
}
__device__ __forceinline__ float ex2(float x) {
    float y;
    asm("ex2.approx.f32 %0, %1;" : "=f"(y) : "f"(x));
    return y;
}

// ---------------------------------------------------------------------------
// fp16 single-pass HMMA GEMM:  D[M,N] = alpha * (A @ B^T) (+ bias / scale)
//   A [M,K] K-major fp16; B [N,K] K-major fp16.
//   CTA 128x256, BK=64 (SW128), 4-stage cp.async (one sync/iter), 8 warps,
//   warp tile 64x64, mma.m16n8k16.
// OUTMODE: 0 = fp32; 2 = fp16;
//          3 = fp16 exp2(v) + deterministic per-CTA row-sum partials in Cf
// BIASMODE: 0 = none; 1 = per column (fp32, batched); 2 = per row;
//           3 = multiply by per-row scale (fp32, batched)
// ---------------------------------------------------------------------------
#define BM 128
#define BN 256
#define BKC 64
#define OFF_B  16384u
#define STAGE  49152u
#define NSTG   4
#define GEMM_SMEM (NSTG * 49152)     // 196608

template<int OUTMODE, int BIASMODE>
__global__ void __launch_bounds__(256, 1) mma_gemm(
    const __half* __restrict__ Ah, const __half* __restrict__ Bh,
    const float* __restrict__ bias,
    float* __restrict__ Cf, __half* __restrict__ Chi,
    int N, int K, float alpha,
    long batchA, long batchB, long batchC, long biasBatch)
{
    extern __shared__ char smem[];
    const uint32_t sbase = smem_u32(smem);
    const int tid  = threadIdx.x;
    const int lane = tid & 31;
    const int wid  = tid >> 5;
    const int wm   = wid >> 2;   // 0..1  (m64)
    const int wn   = wid & 3;    // 0..3  (n64)
    const int row0 = blockIdx.y * BM;
    const int col0 = blockIdx.x * BN;
    const size_t zA = (size_t)blockIdx.z * batchA;
    const size_t zB = (size_t)blockIdx.z * batchB;
    const size_t zC = (size_t)blockIdx.z * batchC;
    const float* bp = bias ? bias + (size_t)blockIdx.z * biasBatch : bias;

    const int r8 = tid >> 3;              // 0..31
    const uint32_t cb = (tid & 7) * 16;   // byte offset within 128B row

    // Hoisted loader invariants: swizzled smem offsets + global row bases.
    uint32_t soA[4], soB[8];
    const char *pA[4], *pB[8];
    #pragma unroll
    for (int i = 0; i < 4; i++) {
        int r = r8 + i * 32;
        soA[i] = sw128((uint32_t)(r * 128) + cb);
        pA[i]  = (const char*)(Ah + zA + (size_t)(row0 + r) * K) + cb;
    }
    #pragma unroll
    for (int i = 0; i < 8; i++) {
        int r = r8 + i * 32;
        soB[i] = sw128((uint32_t)(r * 128) + cb);
        pB[i]  = (const char*)(Bh + zB + (size_t)(col0 + r) * K) + cb;
    }

    auto load_stage = [&](int s, int k0) {
        const uint32_t st = sbase + s * STAGE;
        const size_t kb = (size_t)k0 * 2;          // bytes along K
        #pragma unroll
        for (int i = 0; i < 4; i++)
            cpa16(st + soA[i], pA[i] + kb);
        #pragma unroll
        for (int i = 0; i < 8; i++)
            cpa16(st + OFF_B + soB[i], pB[i] + kb);
        cpa_commit();
    };

    float c[4][8][4];
    #pragma unroll
    for (int i = 0; i < 4; i++)
        #pragma unroll
        for (int j = 0; j < 8; j++)
            #pragma unroll
            for (int k = 0; k < 4; k++) c[i][j][k] = 0.f;

    const int nk = K / BKC;                // >= 12 for all our shapes
    load_stage(0, 0);
    load_stage(1, BKC);
    load_stage(2, 2 * BKC);

    const int a_r = ((lane >> 3) & 1) * 8 + (lane & 7);
    const int a_k = ((lane >> 4) & 1) * 16;
    const int b_r = ((lane >> 4) & 1) * 8 + (lane & 7);
    const int b_k = ((lane >> 3) & 1) * 16;

    for (int i = 0; i < nk; i++) {
        // ensure cp.async group i has completed
        if (i + 3 <= nk)      cpa_wait<2>();
        else if (i + 2 == nk) cpa_wait<1>();
        else                  cpa_wait<0>();
        __syncthreads();                  // stage i%4 ready; (i-1)%4 freed
        if (i + 3 < nk) load_stage((i + 3) % NSTG, (i + 3) * BKC);

        const uint32_t st = sbase + (i % NSTG) * STAGE;
        #pragma unroll
        for (int ks = 0; ks < 4; ks++) {
            uint32_t a_[4][4];
            #pragma unroll
            for (int fm = 0; fm < 4; fm++) {
                int row = wm * 64 + fm * 16 + a_r;
                uint32_t so = sw128((uint32_t)(row * 128) + ks * 32 + a_k);
                ldmx4(a_[fm], st + so);
            }
            uint32_t b_[4][4];
            #pragma unroll
            for (int g = 0; g < 4; g++) {
                int row = wn * 64 + g * 16 + b_r;
                uint32_t so = sw128((uint32_t)(row * 128) + ks * 32 + b_k);
                ldmx4(b_[g], st + OFF_B + so);
            }
            #pragma unroll
            for (int fm = 0; fm < 4; fm++)
                #pragma unroll
                for (int fn = 0; fn < 8; fn++)
                    mma16816(c[fm][fn], a_[fm], &b_[fn >> 1][(fn & 1) * 2]);
        }
    }

    // ---- epilogue -------------------------------------------------------
    float rsum[8];
    if (OUTMODE == 3) {
        #pragma unroll
        for (int r = 0; r < 8; r++) rsum[r] = 0.f;
    }

    #pragma unroll
    for (int fm = 0; fm < 4; fm++)
        #pragma unroll
        for (int fn = 0; fn < 8; fn++) {
            int row = row0 + wm * 64 + fm * 16 + (lane >> 2);
            int col = col0 + wn * 64 + fn * 8 + (lane & 3) * 2;
            float v0 = c[fm][fn][0] * alpha, v1 = c[fm][fn][1] * alpha;
            float v2 = c[fm][fn][2] * alpha, v3 = c[fm][fn][3] * alpha;
            if (BIASMODE == 1) {
                float b0 = bp[col], b1 = bp[col + 1];
                v0 += b0; v1 += b1; v2 += b0; v3 += b1;
            }
            if (BIASMODE == 2) {
                float rb0 = bp[row], rb1 = bp[row + 8];
                v0 += rb0; v1 += rb0; v2 += rb1; v3 += rb1;
            }
            if (BIASMODE == 3) {
                float rb0 = bp[row], rb1 = bp[row + 8];
                v0 *= rb0; v1 *= rb0; v2 *= rb1; v3 *= rb1;
            }
            size_t o0 = zC + (size_t)row * N + col;
            size_t o1 = o0 + (size_t)8 * N;
            if (OUTMODE == 0) {
                *(float2*)(Cf + o0) = make_float2(v0, v1);
                *(float2*)(Cf + o1) = make_float2(v2, v3);
            } else if (OUTMODE == 2) {
                *(uint32_t*)(Chi + o0) = hpack(v0, v1);
                *(uint32_t*)(Chi + o1) = hpack(v2, v3);
            } else {                                  // OUTMODE == 3
                float e0 = ex2(v0), e1 = ex2(v1);
                float e2 = ex2(v2), e3 = ex2(v3);
                *(uint32_t*)(Chi + o0) = hpack(e0, e1);
                *(uint32_t*)(Chi + o1) = hpack(e2, e3);
                rsum[fm * 2]     += e0 + e1;
                rsum[fm * 2 + 1] += e2 + e3;
            }
        }

    if (OUTMODE == 3) {
        // deterministic row-sum reduction -> per-CTA partials
        #pragma unroll
        for (int r = 0; r < 8; r++) {
            rsum[r] += __shfl_xor_sync(0xffffffffu, rsum[r], 1);
            rsum[r] += __shfl_xor_sync(0xffffffffu, rsum[r], 2);
        }
        __syncthreads();                      // safe to reuse stage smem
        float* arr = (float*)smem;            // [4][128]
        if ((lane & 3) == 0) {
            #pragma unroll
            for (int fm = 0; fm < 4; fm++) {
                int r0 = wm * 64 + fm * 16 + (lane >> 2);
                arr[wn * 128 + r0]     = rsum[fm * 2];
                arr[wn * 128 + r0 + 8] = rsum[fm * 2 + 1];
            }
        }
        __syncthreads();
        if (tid < 128) {
            float s = (arr[tid] + arr[128 + tid]) + (arr[256 + tid] + arr[384 + tid]);
            size_t grow = (size_t)blockIdx.z * (gridDim.y * BM) + row0 + tid;
            Cf[grow * gridDim.x + blockIdx.x] = s;
        }
    }
}

// ---------------------------------------------------------------------------
// Merged convert: 4 segments of fp32 -> fp16.  All sizes multiples of 2048.
// ---------------------------------------------------------------------------
__global__ void __launch_bounds__(256) cvt4_kernel(
    const float* __restrict__ s0, __half* __restrict__ d0, unsigned B0,
    const float* __restrict__ s1, __half* __restrict__ d1, unsigned B1,
    const float* __restrict__ s2, __half* __restrict__ d2, unsigned B2,
    const float* __restrict__ s3, __half* __restrict__ d3)
{
    unsigned b = blockIdx.x;
    const float* s; __half* d;
    if (b < B0)                { s = s0; d = d0; }
    else if (b < B0 + B1)      { s = s1; d = d1; b -= B0; }
    else if (b < B0 + B1 + B2) { s = s2; d = d2; b -= B0 + B1; }
    else                       { s = s3; d = d3; b -= B0 + B1 + B2; }
    size_t i = ((size_t)b * 256 + threadIdx.x) * 8;
    float4 v0 = *(const float4*)(s + i);
    float4 v1 = *(const float4*)(s + i + 4);
    uint4 o;
    o.x = hpack(v0.x, v0.y);
    o.y = hpack(v0.z, v0.w);
    o.z = hpack(v1.x, v1.y);
    o.w = hpack(v1.z, v1.w);
    *(uint4*)(d + i) = o;
}

// ---------------------------------------------------------------------------
// Transposed convert: W [K,N] fp32 -> Wt [N,K] fp16   (Wv only)
// ---------------------------------------------------------------------------
__global__ void transpose_cvt_kernel(const float* __restrict__ W,
                                     __half* __restrict__ hi, int K, int N)
{
    __shared__ float t[32][33];
    int n0 = blockIdx.x * 32, k0 = blockIdx.y * 32;
    int x = threadIdx.x, y = threadIdx.y;
    #pragma unroll
    for (int j = 0; j < 32; j += 8)
        t[y + j][x] = W[(size_t)(k0 + y + j) * N + n0 + x];
    __syncthreads();
    #pragma unroll
    for (int j = 0; j < 32; j += 8)
        hi[(size_t)(n0 + y + j) * K + k0 + x] = __float2half_rn(t[x][y + j]);
}

// ---------------------------------------------------------------------------
// w16 = fp16(Wk @ bq)  (dot in fp32, stored fp16).  One block per row.
// ---------------------------------------------------------------------------
__global__ void __launch_bounds__(256) wvec_kernel(
    const float* __restrict__ Wk, const float* __restrict__ bq,
    __half* __restrict__ w16)
{
    const int i = blockIdx.x;
    const int tid = threadIdx.x;
    float s = 0.f;
    #pragma unroll
    for (int j = 0; j < 4; j++) {
        int o = tid + j * 256;
        s += Wk[(size_t)i * SDK + o] * bq[o];
    }
    #pragma unroll
    for (int off = 16; off; off >>= 1)
        s += __shfl_xor_sync(0xffffffffu, s, off);
    __shared__ float red[8];
    if ((tid & 31) == 0) red[tid >> 5] = s;
    __syncthreads();
    if (tid == 0) {
        float t = 0.f;
        #pragma unroll
        for (int k = 0; k < 8; k++) t += red[k];
        w16[i] = __float2half_rn(t);
    }
}

// ---------------------------------------------------------------------------
// cs[j] = dot(kh[j,:], w16) * (log2e/32).  One WARP per row, symmetric
// coalesced uint4 loads from kh and w16 (w16 = 2KB, L1-resident broadcast).
// ---------------------------------------------------------------------------
__global__ void __launch_bounds__(256) cvec_kernel(
    const __half* __restrict__ kh, const __half* __restrict__ w16,
    float* __restrict__ cs)
{
    const int lane = threadIdx.x & 31;
    const size_t row = (size_t)blockIdx.x * 8 + (threadIdx.x >> 5);
    const uint4* kr = (const uint4*)(kh + row * SDK);
    const uint4* wr = (const uint4*)(w16);
    float s = 0.f;
    #pragma unroll
    for (int t = 0; t < 4; t++) {
        uint4 v = kr[lane + t * 32];
        uint4 u = wr[lane + t * 32];
        float2 a0 = __half22float2(*(__half2*)&v.x), b0 = __half22float2(*(__half2*)&u.x);
        float2 a1 = __half22float2(*(__half2*)&v.y), b1 = __half22float2(*(__half2*)&u.y);
        float2 a2 = __half22float2(*(__half2*)&v.z), b2 = __half22float2(*(__half2*)&u.z);
        float2 a3 = __half22float2(*(__half2*)&v.w), b3 = __half22float2(*(__half2*)&u.w);
        s += a0.x * b0.x + a0.y * b0.y + a1.x * b1.x + a1.y * b1.y
           + a2.x * b2.x + a2.y * b2.y + a3.x * b3.x + a3.y * b3.y;
    }
    #pragma unroll
    for (int off = 16; off; off >>= 1)
        s += __shfl_xor_sync(0xffffffffu, s, off);
    if (lane == 0) cs[row] = s * (0.03125f * LOG2E);
}

// ---------------------------------------------------------------------------
// rs[i] = 1 / sum(part[i][0..8))   (deterministic, fixed order)
// ---------------------------------------------------------------------------
__global__ void __launch_bounds__(256) rowinv_kernel(
    const float* __restrict__ part, float* __restrict__ rs)
{
    int i = blockIdx.x * 256 + threadIdx.x;
    const float* p = part + (size_t)i * 8;
    float s = ((p[0] + p[1]) + (p[2] + p[3])) + ((p[4] + p[5]) + (p[6] + p[7]));
    rs[i] = 1.f / s;
}

// ---------------------------------------------------------------------------
// kernel_launch
// ---------------------------------------------------------------------------
extern "C" void kernel_launch(void* const* d_in, const int* in_sizes, int n_in,
                              void* d_out, int out_size)
{
    const float* query = (const float*)d_in[0];
    const float* key   = (const float*)d_in[1];
    const float* Wq    = (const float*)d_in[2];
    const float* bq    = (const float*)d_in[3];
    const float* Wk    = (const float*)d_in[4];
    const float* bk    = (const float*)d_in[5];   // vanishes under softmax
    const float* Wv    = (const float*)d_in[6];
    const float* bv    = (const float*)d_in[7];
    float* out = (float*)d_out;
    (void)bk;

    __half *qh,*kh,*wq16,*wk16,*wvt,*M2,*Kred,*Vth,*Sf,*w16;
    float *cs,*part,*rs;
    cudaGetSymbolAddress((void**)&qh,   g_qh);
    cudaGetSymbolAddress((void**)&kh,   g_kh);
    cudaGetSymbolAddress((void**)&wq16, g_wq16);
    cudaGetSymbolAddress((void**)&wk16, g_wk16);
    cudaGetSymbolAddress((void**)&wvt,  g_wvt);
    cudaGetSymbolAddress((void**)&M2,   g_M2);
    cudaGetSymbolAddress((void**)&Kred, g_Kred);
    cudaGetSymbolAddress((void**)&Vth,  g_Vth);
    cudaGetSymbolAddress((void**)&Sf,   g_Sf);
    cudaGetSymbolAddress((void**)&w16,  g_w16);
    cudaGetSymbolAddress((void**)&cs,   g_cs);
    cudaGetSymbolAddress((void**)&part, g_part);
    cudaGetSymbolAddress((void**)&rs,   g_rs);

    cudaFuncSetAttribute(mma_gemm<2,0>, cudaFuncAttributeMaxDynamicSharedMemorySize, GEMM_SMEM);
    cudaFuncSetAttribute(mma_gemm<2,2>, cudaFuncAttributeMaxDynamicSharedMemorySize, GEMM_SMEM);
    cudaFuncSetAttribute(mma_gemm<3,1>, cudaFuncAttributeMaxDynamicSharedMemorySize, GEMM_SMEM);
    cudaFuncSetAttribute(mma_gemm<0,3>, cudaFuncAttributeMaxDynamicSharedMemorySize, GEMM_SMEM);

    // 1. all fp32->fp16 converts in ONE launch (query, key, Wq, Wk)
    {
        const unsigned Bq  = (unsigned)((size_t)NB * SLQ * SDQ / 2048);  // 12288
        const unsigned Bk  = (unsigned)((size_t)NB * SLK * SDK / 2048);  // 16384
        const unsigned Bwq = (unsigned)((size_t)SDQ * SDK / 2048);       // 384
        const unsigned Bwk = (unsigned)((size_t)SDK * SDK / 2048);       // 512
        cvt4_kernel<<<Bq + Bk + Bwq + Bwk, 256>>>(
            query, qh, Bq, key, kh, Bk, Wq, wq16, Bwq, Wk, wk16);
    }
    transpose_cvt_kernel<<<dim3(SDK/32, SDK/32), dim3(32,8)>>>(Wv, wvt, SDK, SDK);

    // 2. bias column (log2-domain): w16 = fp16(Wk@bq) ; cs = (kh@w16)*log2e/32
    wvec_kernel<<<SDK, 256>>>(Wk, bq, w16);
    cvec_kernel<<<NB*SLK/8, 256>>>(kh, w16, cs);

    // 3. M2 = Wq @ Wk^T  (M=768, N=1024, K=1024) -> fp16
    mma_gemm<2,0><<<dim3(SDK/BN, SDQ/BM, 1), 256, GEMM_SMEM>>>(
        wq16, wk16, nullptr, nullptr, M2, SDK, SDK, 1.f, 0, 0, 0, 0);

    // 4. Kred = key @ M2^T  (M=32768, N=768, K=1024) -> fp16
    mma_gemm<2,0><<<dim3(SDQ/BN, (NB*SLK)/BM, 1), 256, GEMM_SMEM>>>(
        kh, M2, nullptr, nullptr, Kred, SDQ, SDK, 1.f, 0, 0, 0, 0);

    // 5. V projection, transposed out: Vt[b][d][t] (M=1024, N=2048, K=1024)
    mma_gemm<2,2><<<dim3(SLK/BN, SDK/BM, NB), 256, GEMM_SMEM>>>(
        wvt, kh, bv, nullptr, Vth,
        SLK, SDK, 1.f, 0, (long)SLK*SDK, (long)SDK*SLK, 0);

    // 6. Sf = exp2(query @ Kred^T * log2e/32 + cs), plus deterministic
    //    per-CTA row-sum partials
    mma_gemm<3,1><<<dim3(SLK/BN, SLQ/BM, NB), 256, GEMM_SMEM>>>(
        qh, Kred, cs, part, Sf,
        SLK, SDQ, 0.03125f * LOG2E,
        (long)SLQ*SDQ, (long)SLK*SDQ, (long)SLQ*SLK, SLK);

    // 7. row-sum reciprocals
    rowinv_kernel<<<NB*SLQ/256, 256>>>(part, rs);

    // 8. out = (Sf @ Vt^T) * rs[row]  (M=2048, N=1024, K=2048 per batch)
    mma_gemm<0,3><<<dim3(SDK/BN, SLQ/BM, NB), 256, GEMM_SMEM>>>(
        Sf, Vth, rs, out, nullptr,
        SDK, SLK, 1.f, (long)SLQ*SLK, (long)SDK*SLK, (long)SLQ*SDK, SLQ);
}

// round 14
// speedup vs baseline: 1.0371x; 1.0123x over previous
#include <cuda_runtime.h>
#include <cuda_fp16.h>
#include <stdint.h>

#define NB  16
#define SLQ 2048
#define SLK 2048
#define SDQ 768
#define SDK 1024
#define LOG2E 1.4426950408889634f

// ---------------------------------------------------------------------------
// Device-global scratch
// ---------------------------------------------------------------------------
__device__ __half g_qh  [(size_t)NB*SLQ*SDQ];   // fp16(query)
__device__ __half g_kh  [(size_t)NB*SLK*SDK];   // fp16(key)
__device__ __half g_wq16[SDQ*SDK];              // fp16(Wq)   [768,1024]
__device__ __half g_wk16[SDK*SDK];              // fp16(Wk)   [1024,1024]
__device__ __half g_wvt [SDK*SDK];              // fp16(Wv^T) [1024,1024]
__device__ float  g_m2p [(size_t)4*SDQ*SDK];    // M2 split-K fp32 partials
__device__ __half g_M2  [SDQ*SDK];              // Wq@Wk^T    [768,1024]
__device__ __half g_Kred[(size_t)NB*SLK*SDQ];   // key@M2^T   [B*Lk,768]
__device__ __half g_Vth [(size_t)NB*SDK*SLK];   // V^T        [B,Dk,Lk]
__device__ __half g_Sf  [(size_t)NB*SLQ*SLK];   // exp(scores) fp16
__device__ float  g_part[(size_t)NB*SLQ*8];     // per-CTA partial row sums
__device__ __half g_w16 [SDK];                  // fp16(Wk @ bq)
__device__ float  g_cs  [NB*SLK];               // (key@w)/32 * log2e

// ---------------------------------------------------------------------------
// PTX helpers — baseline (non-'a') features only
// ---------------------------------------------------------------------------
__device__ __forceinline__ uint32_t smem_u32(const void* p) {
    uint32_t a;
    asm("{ .reg .u64 t; cvta.to.shared.u64 t, %1; cvt.u32.u64 %0, t; }"
        : "=r"(a) : "l"(p));
    return a;
}
__device__ __forceinline__ void cpa16(uint32_t dst, const void* src) {
    asm volatile("cp.async.cg.shared.global [%0], [%1], 16;"
                 :: "r"(dst), "l"(src) : "memory");
}
__device__ __forceinline__ void cpa_commit() {
    asm volatile("cp.async.commit_group;" ::: "memory");
}
template<int N>
__device__ __forceinline__ void cpa_wait() {
    asm volatile("cp.async.wait_group %0;" :: "n"(N) : "memory");
}
__device__ __forceinline__ void ldmx4(uint32_t* r, uint32_t addr) {
    asm volatile("ldmatrix.sync.aligned.m8n8.x4.shared.b16 {%0,%1,%2,%3}, [%4];"
                 : "=r"(r[0]), "=r"(r[1]), "=r"(r[2]), "=r"(r[3]) : "r"(addr));
}
__device__ __forceinline__ void mma16816(float* c, const uint32_t* a, const uint32_t* b) {
    asm volatile(
        "mma.sync.aligned.m16n8k16.row.col.f32.f16.f16.f32 "
        "{%0,%1,%2,%3}, {%4,%5,%6,%7}, {%8,%9}, {%0,%1,%2,%3};"
        : "+f"(c[0]), "+f"(c[1]), "+f"(c[2]), "+f"(c[3])
        : "r"(a[0]), "r"(a[1]), "r"(a[2]), "r"(a[3]), "r"(b[0]), "r"(b[1]));
}
__device__ __forceinline__ uint32_t sw128(uint32_t o) { return o ^ ((o >> 3) & 0x70); }

__device__ __forceinline__ uint32_t hpack(float x, float y) {
    __half hx = __float2half_rn(x), hy = __float2half_rn(y);
    return (uint32_t)__half_as_ushort(hx) | ((uint32_t)__half_as_ushort(hy) << 16);
}
__device__ __forceinline__ float ex2(float x) {
    float y;
    asm("ex2.approx.f32 %0, %1;" : "=f"(y) : "f"(x));
    return y;
}

// ---------------------------------------------------------------------------
// fp16 single-pass HMMA GEMM:  D[M,N] = alpha * (A @ B^T) (+ bias / scale)
//   A [M,K] K-major fp16; B [N,K] K-major fp16.
//   CTA 128x256, BK=64 (SW128), 4-stage cp.async (one sync/iter), 8 warps,
//   warp tile 64x64, mma.m16n8k16.
//   K = row stride (elements); Kloop = K-extent this CTA accumulates
//   (Kloop < K with batchA/batchB used as intra-row K offsets => split-K).
// OUTMODE: 0 = fp32; 2 = fp16;
//          3 = fp16 exp2(v) + deterministic per-CTA row-sum partials in Cf
// BIASMODE: 0 = none; 1 = per column (fp32, batched); 2 = per row;
//           4 = per-row scale = 1/sum(8 fp32 partials) (batched)
// ---------------------------------------------------------------------------
#define BM 128
#define BN 256
#define BKC 64
#define OFF_B  16384u
#define STAGE  49152u
#define NSTG   4
#define GEMM_SMEM (NSTG * 49152)     // 196608

template<int OUTMODE, int BIASMODE>
__global__ void __launch_bounds__(256, 1) mma_gemm(
    const __half* __restrict__ Ah, const __half* __restrict__ Bh,
    const float* __restrict__ bias,
    float* __restrict__ Cf, __half* __restrict__ Chi,
    int N, int K, int Kloop, float alpha,
    long batchA, long batchB, long batchC, long biasBatch)
{
    extern __shared__ char smem[];
    const uint32_t sbase = smem_u32(smem);
    const int tid  = threadIdx.x;
    const int lane = tid & 31;
    const int wid  = tid >> 5;
    const int wm   = wid >> 2;   // 0..1  (m64)
    const int wn   = wid & 3;    // 0..3  (n64)
    const int row0 = blockIdx.y * BM;
    const int col0 = blockIdx.x * BN;
    const size_t zA = (size_t)blockIdx.z * batchA;
    const size_t zB = (size_t)blockIdx.z * batchB;
    const size_t zC = (size_t)blockIdx.z * batchC;
    const float* bp = bias ? bias + (size_t)blockIdx.z * biasBatch : bias;

    const int r8 = tid >> 3;              // 0..31
    const uint32_t cb = (tid & 7) * 16;   // byte offset within 128B row

    // Hoisted loader invariants: swizzled smem offsets + global row bases.
    uint32_t soA[4], soB[8];
    const char *pA[4], *pB[8];
    #pragma unroll
    for (int i = 0; i < 4; i++) {
        int r = r8 + i * 32;
        soA[i] = sw128((uint32_t)(r * 128) + cb);
        pA[i]  = (const char*)(Ah + zA + (size_t)(row0 + r) * K) + cb;
    }
    #pragma unroll
    for (int i = 0; i < 8; i++) {
        int r = r8 + i * 32;
        soB[i] = sw128((uint32_t)(r * 128) + cb);
        pB[i]  = (const char*)(Bh + zB + (size_t)(col0 + r) * K) + cb;
    }

    auto load_stage = [&](int s, int k0) {
        const uint32_t st = sbase + s * STAGE;
        const size_t kb = (size_t)k0 * 2;          // bytes along K
        #pragma unroll
        for (int i = 0; i < 4; i++)
            cpa16(st + soA[i], pA[i] + kb);
        #pragma unroll
        for (int i = 0; i < 8; i++)
            cpa16(st + OFF_B + soB[i], pB[i] + kb);
        cpa_commit();
    };

    float c[4][8][4];
    #pragma unroll
    for (int i = 0; i < 4; i++)
        #pragma unroll
        for (int j = 0; j < 8; j++)
            #pragma unroll
            for (int k = 0; k < 4; k++) c[i][j][k] = 0.f;

    const int nk = Kloop / BKC;            // >= 4 for all launches
    load_stage(0, 0);
    load_stage(1, BKC);
    load_stage(2, 2 * BKC);

    const int a_r = ((lane >> 3) & 1) * 8 + (lane & 7);
    const int a_k = ((lane >> 4) & 1) * 16;
    const int b_r = ((lane >> 4) & 1) * 8 + (lane & 7);
    const int b_k = ((lane >> 3) & 1) * 16;

    for (int i = 0; i < nk; i++) {
        // ensure cp.async group i has completed
        if (i + 3 <= nk)      cpa_wait<2>();
        else if (i + 2 == nk) cpa_wait<1>();
        else                  cpa_wait<0>();
        __syncthreads();                  // stage i%4 ready; (i-1)%4 freed
        if (i + 3 < nk) load_stage((i + 3) % NSTG, (i + 3) * BKC);

        const uint32_t st = sbase + (i % NSTG) * STAGE;
        #pragma unroll
        for (int ks = 0; ks < 4; ks++) {
            uint32_t a_[4][4];
            #pragma unroll
            for (int fm = 0; fm < 4; fm++) {
                int row = wm * 64 + fm * 16 + a_r;
                uint32_t so = sw128((uint32_t)(row * 128) + ks * 32 + a_k);
                ldmx4(a_[fm], st + so);
            }
            uint32_t b_[4][4];
            #pragma unroll
            for (int g = 0; g < 4; g++) {
                int row = wn * 64 + g * 16 + b_r;
                uint32_t so = sw128((uint32_t)(row * 128) + ks * 32 + b_k);
                ldmx4(b_[g], st + OFF_B + so);
            }
            #pragma unroll
            for (int fm = 0; fm < 4; fm++)
                #pragma unroll
                for (int fn = 0; fn < 8; fn++)
                    mma16816(c[fm][fn], a_[fm], &b_[fn >> 1][(fn & 1) * 2]);
        }
    }

    // ---- epilogue -------------------------------------------------------
    float rsum[8];
    if (OUTMODE == 3) {
        #pragma unroll
        for (int r = 0; r < 8; r++) rsum[r] = 0.f;
    }

    #pragma unroll
    for (int fm = 0; fm < 4; fm++) {
        int rowb = row0 + wm * 64 + fm * 16 + (lane >> 2);
        float rs0 = 0.f, rs1 = 0.f;
        if (BIASMODE == 2) { rs0 = bp[rowb]; rs1 = bp[rowb + 8]; }
        if (BIASMODE == 4) {
            const float* p0 = bp + (size_t)rowb * 8;
            const float* p1 = bp + (size_t)(rowb + 8) * 8;
            float s0 = ((p0[0]+p0[1])+(p0[2]+p0[3])) + ((p0[4]+p0[5])+(p0[6]+p0[7]));
            float s1 = ((p1[0]+p1[1])+(p1[2]+p1[3])) + ((p1[4]+p1[5])+(p1[6]+p1[7]));
            rs0 = 1.f / s0; rs1 = 1.f / s1;
        }
        #pragma unroll
        for (int fn = 0; fn < 8; fn++) {
            int col = col0 + wn * 64 + fn * 8 + (lane & 3) * 2;
            float v0 = c[fm][fn][0] * alpha, v1 = c[fm][fn][1] * alpha;
            float v2 = c[fm][fn][2] * alpha, v3 = c[fm][fn][3] * alpha;
            if (BIASMODE == 1) {
                float b0 = bp[col], b1 = bp[col + 1];
                v0 += b0; v1 += b1; v2 += b0; v3 += b1;
            }
            if (BIASMODE == 2) {
                v0 += rs0; v1 += rs0; v2 += rs1; v3 += rs1;
            }
            if (BIASMODE == 4) {
                v0 *= rs0; v1 *= rs0; v2 *= rs1; v3 *= rs1;
            }
            size_t o0 = zC + (size_t)rowb * N + col;
            size_t o1 = o0 + (size_t)8 * N;
            if (OUTMODE == 0) {
                *(float2*)(Cf + o0) = make_float2(v0, v1);
                *(float2*)(Cf + o1) = make_float2(v2, v3);
            } else if (OUTMODE == 2) {
                *(uint32_t*)(Chi + o0) = hpack(v0, v1);
                *(uint32_t*)(Chi + o1) = hpack(v2, v3);
            } else {                                  // OUTMODE == 3
                float e0 = ex2(v0), e1 = ex2(v1);
                float e2 = ex2(v2), e3 = ex2(v3);
                *(uint32_t*)(Chi + o0) = hpack(e0, e1);
                *(uint32_t*)(Chi + o1) = hpack(e2, e3);
                rsum[fm * 2]     += e0 + e1;
                rsum[fm * 2 + 1] += e2 + e3;
            }
        }
    }

    if (OUTMODE == 3) {
        // deterministic row-sum reduction -> per-CTA partials
        #pragma unroll
        for (int r = 0; r < 8; r++) {
            rsum[r] += __shfl_xor_sync(0xffffffffu, rsum[r], 1);
            rsum[r] += __shfl_xor_sync(0xffffffffu, rsum[r], 2);
        }
        __syncthreads();                      // safe to reuse stage smem
        float* arr = (float*)smem;            // [4][128]
        if ((lane & 3) == 0) {
            #pragma unroll
            for (int fm = 0; fm < 4; fm++) {
                int r0 = wm * 64 + fm * 16 + (lane >> 2);
                arr[wn * 128 + r0]     = rsum[fm * 2];
                arr[wn * 128 + r0 + 8] = rsum[fm * 2 + 1];
            }
        }
        __syncthreads();
        if (tid < 128) {
            float s = (arr[tid] + arr[128 + tid]) + (arr[256 + tid] + arr[384 + tid]);
            size_t grow = (size_t)blockIdx.z * (gridDim.y * BM) + row0 + tid;
            Cf[grow * gridDim.x + blockIdx.x] = s;
        }
    }
}

// ---------------------------------------------------------------------------
// Merged convert: 4 segments of fp32 -> fp16.  All sizes multiples of 2048.
// ---------------------------------------------------------------------------
__global__ void __launch_bounds__(256) cvt4_kernel(
    const float* __restrict__ s0, __half* __restrict__ d0, unsigned B0,
    const float* __restrict__ s1, __half* __restrict__ d1, unsigned B1,
    const float* __restrict__ s2, __half* __restrict__ d2, unsigned B2,
    const float* __restrict__ s3, __half* __restrict__ d3)
{
    unsigned b = blockIdx.x;
    const float* s; __half* d;
    if (b < B0)                { s = s0; d = d0; }
    else if (b < B0 + B1)      { s = s1; d = d1; b -= B0; }
    else if (b < B0 + B1 + B2) { s = s2; d = d2; b -= B0 + B1; }
    else                       { s = s3; d = d3; b -= B0 + B1 + B2; }
    size_t i = ((size_t)b * 256 + threadIdx.x) * 8;
    float4 v0 = *(const float4*)(s + i);
    float4 v1 = *(const float4*)(s + i + 4);
    uint4 o;
    o.x = hpack(v0.x, v0.y);
    o.y = hpack(v0.z, v0.w);
    o.z = hpack(v1.x, v1.y);
    o.w = hpack(v1.z, v1.w);
    *(uint4*)(d + i) = o;
}

// ---------------------------------------------------------------------------
// Transposed convert: W [K,N] fp32 -> Wt [N,K] fp16   (Wv only)
// ---------------------------------------------------------------------------
__global__ void transpose_cvt_kernel(const float* __restrict__ W,
                                     __half* __restrict__ hi, int K, int N)
{
    __shared__ float t[32][33];
    int n0 = blockIdx.x * 32, k0 = blockIdx.y * 32;
    int x = threadIdx.x, y = threadIdx.y;
    #pragma unroll
    for (int j = 0; j < 32; j += 8)
        t[y + j][x] = W[(size_t)(k0 + y + j) * N + n0 + x];
    __syncthreads();
    #pragma unroll
    for (int j = 0; j < 32; j += 8)
        hi[(size_t)(n0 + y + j) * K + k0 + x] = __float2half_rn(t[x][y + j]);
}

// ---------------------------------------------------------------------------
// w16 = fp16(Wk @ bq)  (dot in fp32, stored fp16).  One block per row.
// ---------------------------------------------------------------------------
__global__ void __launch_bounds__(256) wvec_kernel(
    const float* __restrict__ Wk, const float* __restrict__ bq,
    __half* __restrict__ w16)
{
    const int i = blockIdx.x;
    const int tid = threadIdx.x;
    float s = 0.f;
    #pragma unroll
    for (int j = 0; j < 4; j++) {
        int o = tid + j * 256;
        s += Wk[(size_t)i * SDK + o] * bq[o];
    }
    #pragma unroll
    for (int off = 16; off; off >>= 1)
        s += __shfl_xor_sync(0xffffffffu, s, off);
    __shared__ float red[8];
    if ((tid & 31) == 0) red[tid >> 5] = s;
    __syncthreads();
    if (tid == 0) {
        float t = 0.f;
        #pragma unroll
        for (int k = 0; k < 8; k++) t += red[k];
        w16[i] = __float2half_rn(t);
    }
}

// ---------------------------------------------------------------------------
// cs[j] = dot(kh[j,:], w16) * (log2e/32).  One WARP per row, symmetric
// coalesced uint4 loads from kh and w16 (w16 = 2KB, L1-resident broadcast).
// ---------------------------------------------------------------------------
__global__ void __launch_bounds__(256) cvec_kernel(
    const __half* __restrict__ kh, const __half* __restrict__ w16,
    float* __restrict__ cs)
{
    const int lane = threadIdx.x & 31;
    const size_t row = (size_t)blockIdx.x * 8 + (threadIdx.x >> 5);
    const uint4* kr = (const uint4*)(kh + row * SDK);
    const uint4* wr = (const uint4*)(w16);
    float s = 0.f;
    #pragma unroll
    for (int t = 0; t < 4; t++) {
        uint4 v = kr[lane + t * 32];
        uint4 u = wr[lane + t * 32];
        float2 a0 = __half22float2(*(__half2*)&v.x), b0 = __half22float2(*(__half2*)&u.x);
        float2 a1 = __half22float2(*(__half2*)&v.y), b1 = __half22float2(*(__half2*)&u.y);
        float2 a2 = __half22float2(*(__half2*)&v.z), b2 = __half22float2(*(__half2*)&u.z);
        float2 a3 = __half22float2(*(__half2*)&v.w), b3 = __half22float2(*(__half2*)&u.w);
        s += a0.x * b0.x + a0.y * b0.y + a1.x * b1.x + a1.y * b1.y
           + a2.x * b2.x + a2.y * b2.y + a3.x * b3.x + a3.y * b3.y;
    }
    #pragma unroll
    for (int off = 16; off; off >>= 1)
        s += __shfl_xor_sync(0xffffffffu, s, off);
    if (lane == 0) cs[row] = s * (0.03125f * LOG2E);
}

// ---------------------------------------------------------------------------
// M2 split-K reduce: M2[i] = fp16(sum of 4 fp32 partials)
// ---------------------------------------------------------------------------
__global__ void __launch_bounds__(256) m2red_kernel(
    const float* __restrict__ p, __half* __restrict__ out)
{
    const size_t S = (size_t)SDQ * SDK;
    size_t i = (size_t)blockIdx.x * 256 + threadIdx.x;
    float s = (p[i] + p[i + S]) + (p[i + 2 * S] + p[i + 3 * S]);
    out[i] = __float2half_rn(s);
}

// ---------------------------------------------------------------------------
// kernel_launch
// ---------------------------------------------------------------------------
extern "C" void kernel_launch(void* const* d_in, const int* in_sizes, int n_in,
                              void* d_out, int out_size)
{
    const float* query = (const float*)d_in[0];
    const float* key   = (const float*)d_in[1];
    const float* Wq    = (const float*)d_in[2];
    const float* bq    = (const float*)d_in[3];
    const float* Wk    = (const float*)d_in[4];
    const float* bk    = (const float*)d_in[5];   // vanishes under softmax
    const float* Wv    = (const float*)d_in[6];
    const float* bv    = (const float*)d_in[7];
    float* out = (float*)d_out;
    (void)bk;

    __half *qh,*kh,*wq16,*wk16,*wvt,*M2,*Kred,*Vth,*Sf,*w16;
    float *cs,*part,*m2p;
    cudaGetSymbolAddress((void**)&qh,   g_qh);
    cudaGetSymbolAddress((void**)&kh,   g_kh);
    cudaGetSymbolAddress((void**)&wq16, g_wq16);
    cudaGetSymbolAddress((void**)&wk16, g_wk16);
    cudaGetSymbolAddress((void**)&wvt,  g_wvt);
    cudaGetSymbolAddress((void**)&M2,   g_M2);
    cudaGetSymbolAddress((void**)&Kred, g_Kred);
    cudaGetSymbolAddress((void**)&Vth,  g_Vth);
    cudaGetSymbolAddress((void**)&Sf,   g_Sf);
    cudaGetSymbolAddress((void**)&w16,  g_w16);
    cudaGetSymbolAddress((void**)&cs,   g_cs);
    cudaGetSymbolAddress((void**)&part, g_part);
    cudaGetSymbolAddress((void**)&m2p,  g_m2p);

    cudaFuncSetAttribute(mma_gemm<0,0>, cudaFuncAttributeMaxDynamicSharedMemorySize, GEMM_SMEM);
    cudaFuncSetAttribute(mma_gemm<2,0>, cudaFuncAttributeMaxDynamicSharedMemorySize, GEMM_SMEM);
    cudaFuncSetAttribute(mma_gemm<2,2>, cudaFuncAttributeMaxDynamicSharedMemorySize, GEMM_SMEM);
    cudaFuncSetAttribute(mma_gemm<3,1>, cudaFuncAttributeMaxDynamicSharedMemorySize, GEMM_SMEM);
    cudaFuncSetAttribute(mma_gemm<0,4>, cudaFuncAttributeMaxDynamicSharedMemorySize, GEMM_SMEM);

    // 1. all fp32->fp16 converts in ONE launch (query, key, Wq, Wk)
    {
        const unsigned Bq  = (unsigned)((size_t)NB * SLQ * SDQ / 2048);  // 12288
        const unsigned Bk  = (unsigned)((size_t)NB * SLK * SDK / 2048);  // 16384
        const unsigned Bwq = (unsigned)((size_t)SDQ * SDK / 2048);       // 384
        const unsigned Bwk = (unsigned)((size_t)SDK * SDK / 2048);       // 512
        cvt4_kernel<<<Bq + Bk + Bwq + Bwk, 256>>>(
            query, qh, Bq, key, kh, Bk, Wq, wq16, Bwq, Wk, wk16);
    }
    transpose_cvt_kernel<<<dim3(SDK/32, SDK/32), dim3(32,8)>>>(Wv, wvt, SDK, SDK);

    // 2. bias column (log2-domain): w16 = fp16(Wk@bq) ; cs = (kh@w16)*log2e/32
    wvec_kernel<<<SDK, 256>>>(Wk, bq, w16);
    cvec_kernel<<<NB*SLK/8, 256>>>(kh, w16, cs);

    // 3. M2 = Wq @ Wk^T  (M=768, N=1024, K=1024) — split-K x4 (fp32 partials)
    //    z = K-slice; batchA/batchB = 256-element intra-row offsets.
    mma_gemm<0,0><<<dim3(SDK/BN, SDQ/BM, 4), 256, GEMM_SMEM>>>(
        wq16, wk16, nullptr, m2p, nullptr,
        SDK, SDK, /*Kloop=*/256, 1.f,
        256, 256, (long)SDQ*SDK, 0);
    m2red_kernel<<<(SDQ*SDK)/256, 256>>>(m2p, M2);

    // 4. Kred = key @ M2^T  (M=32768, N=768, K=1024) -> fp16
    mma_gemm<2,0><<<dim3(SDQ/BN, (NB*SLK)/BM, 1), 256, GEMM_SMEM>>>(
        kh, M2, nullptr, nullptr, Kred, SDQ, SDK, SDK, 1.f, 0, 0, 0, 0);

    // 5. V projection, transposed out: Vt[b][d][t] (M=1024, N=2048, K=1024)
    mma_gemm<2,2><<<dim3(SLK/BN, SDK/BM, NB), 256, GEMM_SMEM>>>(
        wvt, kh, bv, nullptr, Vth,
        SLK, SDK, SDK, 1.f, 0, (long)SLK*SDK, (long)SDK*SLK, 0);

    // 6. Sf = exp2(query @ Kred^T * log2e/32 + cs), plus deterministic
    //    per-CTA row-sum partials
    mma_gemm<3,1><<<dim3(SLK/BN, SLQ/BM, NB), 256, GEMM_SMEM>>>(
        qh, Kred, cs, part, Sf,
        SLK, SDQ, SDQ, 0.03125f * LOG2E,
        (long)SLQ*SDQ, (long)SLK*SDQ, (long)SLQ*SLK, SLK);

    // 7. out = (Sf @ Vt^T) * (1/rowsum from partials)  (M=2048, N=1024, K=2048)
    mma_gemm<0,4><<<dim3(SDK/BN, SLQ/BM, NB), 256, GEMM_SMEM>>>(
        Sf, Vth, part, out, nullptr,
        SDK, SLK, SLK, 1.f,
        (long)SLQ*SLK, (long)SDK*SLK, (long)SLQ*SDK, (long)SLQ*8);
}

// round 16
// speedup vs baseline: 1.0471x; 1.0097x over previous
#include <cuda_runtime.h>
#include <cuda_fp16.h>
#include <stdint.h>

#define NB  16
#define SLQ 2048
#define SLK 2048
#define SDQ 768
#define SDK 1024
#define LOG2E 1.4426950408889634f

// ---------------------------------------------------------------------------
// Device-global scratch
// ---------------------------------------------------------------------------
__device__ __half g_qh  [(size_t)NB*SLQ*SDQ];   // fp16(query)
__device__ __half g_kh  [(size_t)NB*SLK*SDK];   // fp16(key)
__device__ __half g_wq16[SDQ*SDK];              // fp16(Wq)   [768,1024]
__device__ __half g_wk16[SDK*SDK];              // fp16(Wk)   [1024,1024]
__device__ __half g_wvt [SDK*SDK];              // fp16(Wv^T) [1024,1024]
__device__ float  g_m2p [(size_t)4*SDQ*SDK];    // M2 split-K fp32 partials
__device__ __half g_M2  [SDQ*SDK];              // Wq@Wk^T    [768,1024]
__device__ __half g_Kred[(size_t)NB*SLK*SDQ];   // key@M2^T   [B*Lk,768]
__device__ __half g_Vth [(size_t)NB*SDK*SLK];   // V^T        [B,Dk,Lk]
__device__ __half g_Sf  [(size_t)NB*SLQ*SLK];   // exp(scores) fp16
__device__ float  g_part[(size_t)NB*SLQ*8];     // per-CTA partial row sums
__device__ __half g_w16 [SDK];                  // fp16(Wk @ bq)
__device__ float  g_cs  [NB*SLK];               // (key@w)/32 * log2e

// ---------------------------------------------------------------------------
// PTX helpers — baseline (non-'a') features only
// ---------------------------------------------------------------------------
__device__ __forceinline__ uint32_t smem_u32(const void* p) {
    uint32_t a;
    asm("{ .reg .u64 t; cvta.to.shared.u64 t, %1; cvt.u32.u64 %0, t; }"
        : "=r"(a) : "l"(p));
    return a;
}
__device__ __forceinline__ void cpa16(uint32_t dst, const void* src) {
    asm volatile("cp.async.cg.shared.global [%0], [%1], 16;"
                 :: "r"(dst), "l"(src) : "memory");
}
__device__ __forceinline__ void cpa_commit() {
    asm volatile("cp.async.commit_group;" ::: "memory");
}
template<int N>
__device__ __forceinline__ void cpa_wait() {
    asm volatile("cp.async.wait_group %0;" :: "n"(N) : "memory");
}
__device__ __forceinline__ void ldmx4(uint32_t* r, uint32_t addr) {
    asm volatile("ldmatrix.sync.aligned.m8n8.x4.shared.b16 {%0,%1,%2,%3}, [%4];"
                 : "=r"(r[0]), "=r"(r[1]), "=r"(r[2]), "=r"(r[3]) : "r"(addr));
}
__device__ __forceinline__ void mma16816(float* c, const uint32_t* a, const uint32_t* b) {
    asm volatile(
        "mma.sync.aligned.m16n8k16.row.col.f32.f16.f16.f32 "
        "{%0,%1,%2,%3}, {%4,%5,%6,%7}, {%8,%9}, {%0,%1,%2,%3};"
        : "+f"(c[0]), "+f"(c[1]), "+f"(c[2]), "+f"(c[3])
        : "r"(a[0]), "r"(a[1]), "r"(a[2]), "r"(a[3]), "r"(b[0]), "r"(b[1]));
}
__device__ __forceinline__ uint32_t sw128(uint32_t o) { return o ^ ((o >> 3) & 0x70); }

__device__ __forceinline__ uint32_t hpack(float x, float y) {
    __half hx = __float2half_rn(x), hy = __float2half_rn(y);
    return (uint32_t)__half_as_ushort(hx) | ((uint32_t)__half_as_ushort(hy) << 16);
}
__device__ __forceinline__ float ex2(float x) {
    float y;
    asm("ex2.approx.f32 %0, %1;" : "=f"(y) : "f"(x));
    return y;
}

// ---------------------------------------------------------------------------
// fp16 single-pass HMMA GEMM:  D[M,N] = alpha * (A @ B^T) (+ bias / scale)
//   A [M,K] K-major fp16; B [N,K] K-major fp16.
//   CTA 128x256, BK=64 (SW128), 4-stage cp.async (one sync/iter), 8 warps,
//   warp tile 64x64, mma.m16n8k16.
//   K = row stride (elements); Kloop = K-extent this CTA accumulates
//   (Kloop < K with batchA/batchB used as intra-row K offsets => split-K).
// OUTMODE: 0 = fp32; 2 = fp16;
//          3 = fp16 exp2(v) + deterministic per-CTA row-sum partials in Cf
// BIASMODE: 0 = none; 1 = per column (fp32, batched); 2 = per row;
//           4 = per-row scale = 1/sum(8 fp32 partials) (batched)
// ---------------------------------------------------------------------------
#define BM 128
#define BN 256
#define BKC 64
#define OFF_B  16384u
#define STAGE  49152u
#define NSTG   4
#define GEMM_SMEM (NSTG * 49152)     // 196608

template<int OUTMODE, int BIASMODE>
__global__ void __launch_bounds__(256, 1) mma_gemm(
    const __half* __restrict__ Ah, const __half* __restrict__ Bh,
    const float* __restrict__ bias,
    float* __restrict__ Cf, __half* __restrict__ Chi,
    int N, int K, int Kloop, float alpha,
    long batchA, long batchB, long batchC, long biasBatch)
{
    extern __shared__ char smem[];
    const uint32_t sbase = smem_u32(smem);
    const int tid  = threadIdx.x;
    const int lane = tid & 31;
    const int wid  = tid >> 5;
    const int wm   = wid >> 2;   // 0..1  (m64)
    const int wn   = wid & 3;    // 0..3  (n64)
    const int row0 = blockIdx.y * BM;
    const int col0 = blockIdx.x * BN;
    const size_t zA = (size_t)blockIdx.z * batchA;
    const size_t zB = (size_t)blockIdx.z * batchB;
    const size_t zC = (size_t)blockIdx.z * batchC;
    const float* bp = bias ? bias + (size_t)blockIdx.z * biasBatch : bias;

    const int r8 = tid >> 3;              // 0..31
    const uint32_t cb = (tid & 7) * 16;   // byte offset within 128B row

    // Hoisted loader invariants: swizzled smem offsets + global row bases.
    uint32_t soA[4], soB[8];
    const char *pA[4], *pB[8];
    #pragma unroll
    for (int i = 0; i < 4; i++) {
        int r = r8 + i * 32;
        soA[i] = sw128((uint32_t)(r * 128) + cb);
        pA[i]  = (const char*)(Ah + zA + (size_t)(row0 + r) * K) + cb;
    }
    #pragma unroll
    for (int i = 0; i < 8; i++) {
        int r = r8 + i * 32;
        soB[i] = sw128((uint32_t)(r * 128) + cb);
        pB[i]  = (const char*)(Bh + zB + (size_t)(col0 + r) * K) + cb;
    }

    auto load_stage = [&](int s, int k0) {
        const uint32_t st = sbase + s * STAGE;
        const size_t kb = (size_t)k0 * 2;          // bytes along K
        #pragma unroll
        for (int i = 0; i < 4; i++)
            cpa16(st + soA[i], pA[i] + kb);
        #pragma unroll
        for (int i = 0; i < 8; i++)
            cpa16(st + OFF_B + soB[i], pB[i] + kb);
        cpa_commit();
    };

    float c[4][8][4];
    #pragma unroll
    for (int i = 0; i < 4; i++)
        #pragma unroll
        for (int j = 0; j < 8; j++)
            #pragma unroll
            for (int k = 0; k < 4; k++) c[i][j][k] = 0.f;

    const int nk = Kloop / BKC;            // >= 4 for all launches
    load_stage(0, 0);
    load_stage(1, BKC);
    load_stage(2, 2 * BKC);

    const int a_r = ((lane >> 3) & 1) * 8 + (lane & 7);
    const int a_k = ((lane >> 4) & 1) * 16;
    const int b_r = ((lane >> 4) & 1) * 8 + (lane & 7);
    const int b_k = ((lane >> 3) & 1) * 16;

    for (int i = 0; i < nk; i++) {
        // ensure cp.async group i has completed
        if (i + 3 <= nk)      cpa_wait<2>();
        else if (i + 2 == nk) cpa_wait<1>();
        else                  cpa_wait<0>();
        __syncthreads();                  // stage i%4 ready; (i-1)%4 freed
        if (i + 3 < nk) load_stage((i + 3) % NSTG, (i + 3) * BKC);

        const uint32_t st = sbase + (i % NSTG) * STAGE;
        #pragma unroll
        for (int ks = 0; ks < 4; ks++) {
            uint32_t a_[4][4];
            #pragma unroll
            for (int fm = 0; fm < 4; fm++) {
                int row = wm * 64 + fm * 16 + a_r;
                uint32_t so = sw128((uint32_t)(row * 128) + ks * 32 + a_k);
                ldmx4(a_[fm], st + so);
            }
            uint32_t b_[4][4];
            #pragma unroll
            for (int g = 0; g < 4; g++) {
                int row = wn * 64 + g * 16 + b_r;
                uint32_t so = sw128((uint32_t)(row * 128) + ks * 32 + b_k);
                ldmx4(b_[g], st + OFF_B + so);
            }
            #pragma unroll
            for (int fm = 0; fm < 4; fm++)
                #pragma unroll
                for (int fn = 0; fn < 8; fn++)
                    mma16816(c[fm][fn], a_[fm], &b_[fn >> 1][(fn & 1) * 2]);
        }
    }

    // ---- epilogue -------------------------------------------------------
    float rsum[8];
    if (OUTMODE == 3) {
        #pragma unroll
        for (int r = 0; r < 8; r++) rsum[r] = 0.f;
    }

    #pragma unroll
    for (int fm = 0; fm < 4; fm++) {
        int rowb = row0 + wm * 64 + fm * 16 + (lane >> 2);
        float rs0 = 0.f, rs1 = 0.f;
        if (BIASMODE == 2) { rs0 = bp[rowb]; rs1 = bp[rowb + 8]; }
        if (BIASMODE == 4) {
            const float* p0 = bp + (size_t)rowb * 8;
            const float* p1 = bp + (size_t)(rowb + 8) * 8;
            float s0 = ((p0[0]+p0[1])+(p0[2]+p0[3])) + ((p0[4]+p0[5])+(p0[6]+p0[7]));
            float s1 = ((p1[0]+p1[1])+(p1[2]+p1[3])) + ((p1[4]+p1[5])+(p1[6]+p1[7]));
            rs0 = 1.f / s0; rs1 = 1.f / s1;
        }
        #pragma unroll
        for (int fn = 0; fn < 8; fn++) {
            int col = col0 + wn * 64 + fn * 8 + (lane & 3) * 2;
            float v0 = c[fm][fn][0] * alpha, v1 = c[fm][fn][1] * alpha;
            float v2 = c[fm][fn][2] * alpha, v3 = c[fm][fn][3] * alpha;
            if (BIASMODE == 1) {
                float b0 = bp[col], b1 = bp[col + 1];
                v0 += b0; v1 += b1; v2 += b0; v3 += b1;
            }
            if (BIASMODE == 2) {
                v0 += rs0; v1 += rs0; v2 += rs1; v3 += rs1;
            }
            if (BIASMODE == 4) {
                v0 *= rs0; v1 *= rs0; v2 *= rs1; v3 *= rs1;
            }
            size_t o0 = zC + (size_t)rowb * N + col;
            size_t o1 = o0 + (size_t)8 * N;
            if (OUTMODE == 0) {
                *(float2*)(Cf + o0) = make_float2(v0, v1);
                *(float2*)(Cf + o1) = make_float2(v2, v3);
            } else if (OUTMODE == 2) {
                *(uint32_t*)(Chi + o0) = hpack(v0, v1);
                *(uint32_t*)(Chi + o1) = hpack(v2, v3);
            } else {                                  // OUTMODE == 3
                float e0 = ex2(v0), e1 = ex2(v1);
                float e2 = ex2(v2), e3 = ex2(v3);
                *(uint32_t*)(Chi + o0) = hpack(e0, e1);
                *(uint32_t*)(Chi + o1) = hpack(e2, e3);
                rsum[fm * 2]     += e0 + e1;
                rsum[fm * 2 + 1] += e2 + e3;
            }
        }
    }

    if (OUTMODE == 3) {
        // deterministic row-sum reduction -> per-CTA partials
        #pragma unroll
        for (int r = 0; r < 8; r++) {
            rsum[r] += __shfl_xor_sync(0xffffffffu, rsum[r], 1);
            rsum[r] += __shfl_xor_sync(0xffffffffu, rsum[r], 2);
        }
        __syncthreads();                      // safe to reuse stage smem
        float* arr = (float*)smem;            // [4][128]
        if ((lane & 3) == 0) {
            #pragma unroll
            for (int fm = 0; fm < 4; fm++) {
                int r0 = wm * 64 + fm * 16 + (lane >> 2);
                arr[wn * 128 + r0]     = rsum[fm * 2];
                arr[wn * 128 + r0 + 8] = rsum[fm * 2 + 1];
            }
        }
        __syncthreads();
        if (tid < 128) {
            float s = (arr[tid] + arr[128 + tid]) + (arr[256 + tid] + arr[384 + tid]);
            size_t grow = (size_t)blockIdx.z * (gridDim.y * BM) + row0 + tid;
            Cf[grow * gridDim.x + blockIdx.x] = s;
        }
    }
}

// ---------------------------------------------------------------------------
// Merged convert: 4 segments fp32->fp16; the KEY segment also computes
// cs[row] = dot(fp16(key_row), w16) * log2e/32 (2 rows per CTA, deterministic).
// All segment sizes are multiples of 2048; key rows are SDK=1024 elems.
// ---------------------------------------------------------------------------
__global__ void __launch_bounds__(256) cvt4_kernel(
    const float* __restrict__ s0, __half* __restrict__ d0, unsigned B0,
    const float* __restrict__ s1, __half* __restrict__ d1, unsigned B1,
    const float* __restrict__ s2, __half* __restrict__ d2, unsigned B2,
    const float* __restrict__ s3, __half* __restrict__ d3,
    const __half* __restrict__ w16, float* __restrict__ cs)
{
    unsigned b = blockIdx.x;
    const float* s; __half* d;
    bool iskey = false;
    unsigned kb = 0;
    if (b < B0)                { s = s0; d = d0; }
    else if (b < B0 + B1)      { s = s1; d = d1; b -= B0; iskey = true; kb = b; }
    else if (b < B0 + B1 + B2) { s = s2; d = d2; b -= B0 + B1; }
    else                       { s = s3; d = d3; b -= B0 + B1 + B2; }
    const int tid = threadIdx.x;
    size_t i = ((size_t)b * 256 + tid) * 8;
    float4 v0 = *(const float4*)(s + i);
    float4 v1 = *(const float4*)(s + i + 4);
    uint4 o;
    o.x = hpack(v0.x, v0.y);
    o.y = hpack(v0.z, v0.w);
    o.z = hpack(v1.x, v1.y);
    o.w = hpack(v1.z, v1.w);
    *(uint4*)(d + i) = o;

    if (iskey) {
        // block covers key rows 2*kb (threads 0-127) and 2*kb+1 (threads 128-255);
        // thread handles row elements (tid&127)*8..+7 -> w16 uint4 index (tid&127)
        const uint4* wr = (const uint4*)w16;
        uint4 u = wr[tid & 127];
        float2 a0 = __half22float2(*(__half2*)&o.x), b0 = __half22float2(*(__half2*)&u.x);
        float2 a1 = __half22float2(*(__half2*)&o.y), b1 = __half22float2(*(__half2*)&u.y);
        float2 a2 = __half22float2(*(__half2*)&o.z), b2 = __half22float2(*(__half2*)&u.z);
        float2 a3 = __half22float2(*(__half2*)&o.w), b3 = __half22float2(*(__half2*)&u.w);
        float sdot = a0.x * b0.x + a0.y * b0.y + a1.x * b1.x + a1.y * b1.y
                   + a2.x * b2.x + a2.y * b2.y + a3.x * b3.x + a3.y * b3.y;
        #pragma unroll
        for (int off = 16; off; off >>= 1)
            sdot += __shfl_xor_sync(0xffffffffu, sdot, off);
        __shared__ float red[8];
        if ((tid & 31) == 0) red[tid >> 5] = sdot;
        __syncthreads();
        if ((tid & 127) == 0) {
            int h = tid >> 7;                       // 0 or 1 (row within pair)
            float t = (red[h*4] + red[h*4+1]) + (red[h*4+2] + red[h*4+3]);
            cs[(size_t)kb * 2 + h] = t * (0.03125f * LOG2E);
        }
    }
}

// ---------------------------------------------------------------------------
// Transposed convert: W [K,N] fp32 -> Wt [N,K] fp16   (Wv only)
// ---------------------------------------------------------------------------
__global__ void transpose_cvt_kernel(const float* __restrict__ W,
                                     __half* __restrict__ hi, int K, int N)
{
    __shared__ float t[32][33];
    int n0 = blockIdx.x * 32, k0 = blockIdx.y * 32;
    int x = threadIdx.x, y = threadIdx.y;
    #pragma unroll
    for (int j = 0; j < 32; j += 8)
        t[y + j][x] = W[(size_t)(k0 + y + j) * N + n0 + x];
    __syncthreads();
    #pragma unroll
    for (int j = 0; j < 32; j += 8)
        hi[(size_t)(n0 + y + j) * K + k0 + x] = __float2half_rn(t[x][y + j]);
}

// ---------------------------------------------------------------------------
// w16 = fp16(Wk @ bq)  (dot in fp32, stored fp16).  One block per row.
// ---------------------------------------------------------------------------
__global__ void __launch_bounds__(256) wvec_kernel(
    const float* __restrict__ Wk, const float* __restrict__ bq,
    __half* __restrict__ w16)
{
    const int i = blockIdx.x;
    const int tid = threadIdx.x;
    float s = 0.f;
    #pragma unroll
    for (int j = 0; j < 4; j++) {
        int o = tid + j * 256;
        s += Wk[(size_t)i * SDK + o] * bq[o];
    }
    #pragma unroll
    for (int off = 16; off; off >>= 1)
        s += __shfl_xor_sync(0xffffffffu, s, off);
    __shared__ float red[8];
    if ((tid & 31) == 0) red[tid >> 5] = s;
    __syncthreads();
    if (tid == 0) {
        float t = 0.f;
        #pragma unroll
        for (int k = 0; k < 8; k++) t += red[k];
        w16[i] = __float2half_rn(t);
    }
}

// ---------------------------------------------------------------------------
// M2 split-K reduce: M2[i] = fp16(sum of 4 fp32 partials)
// ---------------------------------------------------------------------------
__global__ void __launch_bounds__(256) m2red_kernel(
    const float* __restrict__ p, __half* __restrict__ out)
{
    const size_t S = (size_t)SDQ * SDK;
    size_t i = (size_t)blockIdx.x * 256 + threadIdx.x;
    float s = (p[i] + p[i + S]) + (p[i + 2 * S] + p[i + 3 * S]);
    out[i] = __float2half_rn(s);
}

// ---------------------------------------------------------------------------
// kernel_launch
// ---------------------------------------------------------------------------
extern "C" void kernel_launch(void* const* d_in, const int* in_sizes, int n_in,
                              void* d_out, int out_size)
{
    const float* query = (const float*)d_in[0];
    const float* key   = (const float*)d_in[1];
    const float* Wq    = (const float*)d_in[2];
    const float* bq    = (const float*)d_in[3];
    const float* Wk    = (const float*)d_in[4];
    const float* bk    = (const float*)d_in[5];   // vanishes under softmax
    const float* Wv    = (const float*)d_in[6];
    const float* bv    = (const float*)d_in[7];
    float* out = (float*)d_out;
    (void)bk;

    __half *qh,*kh,*wq16,*wk16,*wvt,*M2,*Kred,*Vth,*Sf,*w16;
    float *cs,*part,*m2p;
    cudaGetSymbolAddress((void**)&qh,   g_qh);
    cudaGetSymbolAddress((void**)&kh,   g_kh);
    cudaGetSymbolAddress((void**)&wq16, g_wq16);
    cudaGetSymbolAddress((void**)&wk16, g_wk16);
    cudaGetSymbolAddress((void**)&wvt,  g_wvt);
    cudaGetSymbolAddress((void**)&M2,   g_M2);
    cudaGetSymbolAddress((void**)&Kred, g_Kred);
    cudaGetSymbolAddress((void**)&Vth,  g_Vth);
    cudaGetSymbolAddress((void**)&Sf,   g_Sf);
    cudaGetSymbolAddress((void**)&w16,  g_w16);
    cudaGetSymbolAddress((void**)&cs,   g_cs);
    cudaGetSymbolAddress((void**)&part, g_part);
    cudaGetSymbolAddress((void**)&m2p,  g_m2p);

    cudaFuncSetAttribute(mma_gemm<0,0>, cudaFuncAttributeMaxDynamicSharedMemorySize, GEMM_SMEM);
    cudaFuncSetAttribute(mma_gemm<2,0>, cudaFuncAttributeMaxDynamicSharedMemorySize, GEMM_SMEM);
    cudaFuncSetAttribute(mma_gemm<2,2>, cudaFuncAttributeMaxDynamicSharedMemorySize, GEMM_SMEM);
    cudaFuncSetAttribute(mma_gemm<3,1>, cudaFuncAttributeMaxDynamicSharedMemorySize, GEMM_SMEM);
    cudaFuncSetAttribute(mma_gemm<0,4>, cudaFuncAttributeMaxDynamicSharedMemorySize, GEMM_SMEM);

    // 1. w16 = fp16(Wk @ bq)  (needed by the fused convert below)
    wvec_kernel<<<SDK, 256>>>(Wk, bq, w16);

    // 2. all fp32->fp16 converts in ONE launch; key segment also emits cs
    {
        const unsigned Bq  = (unsigned)((size_t)NB * SLQ * SDQ / 2048);  // 12288
        const unsigned Bk  = (unsigned)((size_t)NB * SLK * SDK / 2048);  // 16384
        const unsigned Bwq = (unsigned)((size_t)SDQ * SDK / 2048);       // 384
        const unsigned Bwk = (unsigned)((size_t)SDK * SDK / 2048);       // 512
        cvt4_kernel<<<Bq + Bk + Bwq + Bwk, 256>>>(
            query, qh, Bq, key, kh, Bk, Wq, wq16, Bwq, Wk, wk16, w16, cs);
    }
    transpose_cvt_kernel<<<dim3(SDK/32, SDK/32), dim3(32,8)>>>(Wv, wvt, SDK, SDK);

    // 3. M2 = Wq @ Wk^T  (M=768, N=1024, K=1024) — split-K x4 (fp32 partials)
    mma_gemm<0,0><<<dim3(SDK/BN, SDQ/BM, 4), 256, GEMM_SMEM>>>(
        wq16, wk16, nullptr, m2p, nullptr,
        SDK, SDK, /*Kloop=*/256, 1.f,
        256, 256, (long)SDQ*SDK, 0);
    m2red_kernel<<<(SDQ*SDK)/256, 256>>>(m2p, M2);

    // 4. Kred = key @ M2^T  (M=32768, N=768, K=1024) -> fp16
    mma_gemm<2,0><<<dim3(SDQ/BN, (NB*SLK)/BM, 1), 256, GEMM_SMEM>>>(
        kh, M2, nullptr, nullptr, Kred, SDQ, SDK, SDK, 1.f, 0, 0, 0, 0);

    // 5. V projection, transposed out: Vt[b][d][t] (M=1024, N=2048, K=1024)
    mma_gemm<2,2><<<dim3(SLK/BN, SDK/BM, NB), 256, GEMM_SMEM>>>(
        wvt, kh, bv, nullptr, Vth,
        SLK, SDK, SDK, 1.f, 0, (long)SLK*SDK, (long)SDK*SLK, 0);

    // 6. Sf = exp2(query @ Kred^T * log2e/32 + cs), plus deterministic
    //    per-CTA row-sum partials
    mma_gemm<3,1><<<dim3(SLK/BN, SLQ/BM, NB), 256, GEMM_SMEM>>>(
        qh, Kred, cs, part, Sf,
        SLK, SDQ, SDQ, 0.03125f * LOG2E,
        (long)SLQ*SDQ, (long)SLK*SDQ, (long)SLQ*SLK, SLK);

    // 7. out = (Sf @ Vt^T) * (1/rowsum from partials)  (M=2048, N=1024, K=2048)
    mma_gemm<0,4><<<dim3(SDK/BN, SLQ/BM, NB), 256, GEMM_SMEM>>>(
        Sf, Vth, part, out, nullptr,
        SDK, SLK, SLK, 1.f,
        (long)SLQ*SLK, (long)SDK*SLK, (long)SLQ*SDK, (long)SLQ*8);
}

// round 17
// speedup vs baseline: 1.0788x; 1.0303x over previous
#include <cuda_runtime.h>
#include <cuda_fp16.h>
#include <stdint.h>

#define NB  16
#define SLQ 2048
#define SLK 2048
#define SDQ 768
#define SDK 1024
#define LOG2E 1.4426950408889634f

// ---------------------------------------------------------------------------
// Device-global scratch
// ---------------------------------------------------------------------------
__device__ __half g_qh  [(size_t)NB*SLQ*SDQ];   // fp16(query)
__device__ __half g_kh  [(size_t)NB*SLK*SDK];   // fp16(key)
__device__ __half g_wq16[SDQ*SDK];              // fp16(Wq)   [768,1024]
__device__ __half g_wk16[SDK*SDK];              // fp16(Wk)   [1024,1024]
__device__ __half g_wvt [SDK*SDK];              // fp16(Wv^T) [1024,1024]
__device__ float  g_m2p [(size_t)4*SDQ*SDK];    // M2 split-K fp32 partials
__device__ __half g_M2  [SDQ*SDK];              // Wq@Wk^T    [768,1024]
__device__ __half g_Kred[(size_t)NB*SLK*SDQ];   // key@M2^T   [B*Lk,768]
__device__ __half g_Vth [(size_t)NB*SDK*SLK];   // V^T        [B,Dk,Lk]
__device__ __half g_Sf  [(size_t)NB*SLQ*SLK];   // exp(scores) fp16
__device__ float  g_part[(size_t)NB*SLQ*16];    // per-CTA partial row sums
__device__ __half g_w16 [SDK];                  // fp16(Wk @ bq)
__device__ float  g_cs  [NB*SLK];               // (key@w)/32 * log2e

// ---------------------------------------------------------------------------
// PTX helpers — baseline (non-'a') features only
// ---------------------------------------------------------------------------
__device__ __forceinline__ uint32_t smem_u32(const void* p) {
    uint32_t a;
    asm("{ .reg .u64 t; cvta.to.shared.u64 t, %1; cvt.u32.u64 %0, t; }"
        : "=r"(a) : "l"(p));
    return a;
}
__device__ __forceinline__ void cpa16(uint32_t dst, const void* src) {
    asm volatile("cp.async.cg.shared.global [%0], [%1], 16;"
                 :: "r"(dst), "l"(src) : "memory");
}
__device__ __forceinline__ void cpa_commit() {
    asm volatile("cp.async.commit_group;" ::: "memory");
}
template<int N>
__device__ __forceinline__ void cpa_wait() {
    asm volatile("cp.async.wait_group %0;" :: "n"(N) : "memory");
}
__device__ __forceinline__ void ldmx4(uint32_t* r, uint32_t addr) {
    asm volatile("ldmatrix.sync.aligned.m8n8.x4.shared.b16 {%0,%1,%2,%3}, [%4];"
                 : "=r"(r[0]), "=r"(r[1]), "=r"(r[2]), "=r"(r[3]) : "r"(addr));
}
__device__ __forceinline__ void mma16816(float* c, const uint32_t* a, const uint32_t* b) {
    asm volatile(
        "mma.sync.aligned.m16n8k16.row.col.f32.f16.f16.f32 "
        "{%0,%1,%2,%3}, {%4,%5,%6,%7}, {%8,%9}, {%0,%1,%2,%3};"
        : "+f"(c[0]), "+f"(c[1]), "+f"(c[2]), "+f"(c[3])
        : "r"(a[0]), "r"(a[1]), "r"(a[2]), "r"(a[3]), "r"(b[0]), "r"(b[1]));
}
__device__ __forceinline__ uint32_t sw128(uint32_t o) { return o ^ ((o >> 3) & 0x70); }

__device__ __forceinline__ uint32_t hpack(float x, float y) {
    __half hx = __float2half_rn(x), hy = __float2half_rn(y);
    return (uint32_t)__half_as_ushort(hx) | ((uint32_t)__half_as_ushort(hy) << 16);
}
__device__ __forceinline__ float ex2(float x) {
    float y;
    asm("ex2.approx.f32 %0, %1;" : "=f"(y) : "f"(x));
    return y;
}

// ---------------------------------------------------------------------------
// fp16 single-pass HMMA GEMM:  D[M,N] = alpha * (A @ B^T) (+ bias / scale)
//   A [M,K] K-major fp16; B [N,K] K-major fp16.
//   CTA 128x128, BK=64 (SW128), 3-stage cp.async, 8 warps (2m x 4n),
//   warp tile 64x32, mma.m16n8k16.  2 CTAs/SM (96KB smem, <=128 regs).
//   Kloop < K with batchA/batchB as intra-row K offsets => split-K.
// OUTMODE: 0 = fp32; 2 = fp16;
//          3 = fp16 exp2(v) + deterministic per-CTA row-sum partials in Cf
// BIASMODE: 0 = none; 1 = per column (fp32, batched); 2 = per row;
//           4 = per-row scale = 1/sum(16 fp32 partials) (batched)
// ---------------------------------------------------------------------------
#define BM 128
#define BN 128
#define BKC 64
#define OFF_B  16384u
#define STAGE  32768u
#define NSTG   3
#define GEMM_SMEM (NSTG * 32768)     // 98304 -> 2 CTAs/SM

template<int OUTMODE, int BIASMODE>
__global__ void __launch_bounds__(256, 2) mma_gemm(
    const __half* __restrict__ Ah, const __half* __restrict__ Bh,
    const float* __restrict__ bias,
    float* __restrict__ Cf, __half* __restrict__ Chi,
    int N, int K, int Kloop, float alpha,
    long batchA, long batchB, long batchC, long biasBatch)
{
    extern __shared__ char smem[];
    const uint32_t sbase = smem_u32(smem);
    const int tid  = threadIdx.x;
    const int lane = tid & 31;
    const int wid  = tid >> 5;
    const int wm   = wid >> 2;   // 0..1  (m64)
    const int wn   = wid & 3;    // 0..3  (n32)
    const int row0 = blockIdx.y * BM;
    const int col0 = blockIdx.x * BN;
    const float* bp = bias ? bias + (size_t)blockIdx.z * biasBatch : bias;

    const int r8 = tid >> 3;              // 0..31
    const uint32_t cb = (tid & 7) * 16;   // byte offset within 128B row

    const char* pAbase = (const char*)(Ah + (size_t)blockIdx.z * batchA
                                          + (size_t)row0 * K) + cb;
    const char* pBbase = (const char*)(Bh + (size_t)blockIdx.z * batchB
                                          + (size_t)col0 * K) + cb;
    const size_t zC = (size_t)blockIdx.z * batchC;
    const size_t rowbytes = (size_t)K * 2;

    auto load_stage = [&](int s, int k0) {
        const uint32_t st = sbase + s * STAGE;
        const size_t kb = (size_t)k0 * 2;
        #pragma unroll
        for (int i = 0; i < 4; i++) {
            int r = r8 + i * 32;
            uint32_t so = sw128((uint32_t)(r * 128) + cb);
            cpa16(st + so,          pAbase + (size_t)r * rowbytes + kb);
            cpa16(st + OFF_B + so,  pBbase + (size_t)r * rowbytes + kb);
        }
        cpa_commit();
    };

    float c[4][4][4];
    #pragma unroll
    for (int i = 0; i < 4; i++)
        #pragma unroll
        for (int j = 0; j < 4; j++)
            #pragma unroll
            for (int k = 0; k < 4; k++) c[i][j][k] = 0.f;

    const int nk = Kloop / BKC;
    load_stage(0, 0);
    load_stage(1, BKC);

    const int a_r = ((lane >> 3) & 1) * 8 + (lane & 7);
    const int a_k = ((lane >> 4) & 1) * 16;
    const int b_r = ((lane >> 4) & 1) * 8 + (lane & 7);
    const int b_k = ((lane >> 3) & 1) * 16;

    for (int i = 0; i < nk; i++) {
        if (i + 1 < nk) cpa_wait<1>(); else cpa_wait<0>();
        __syncthreads();                  // stage i%3 ready; (i-1)%3 freed
        if (i + 2 < nk) load_stage((i + 2) % NSTG, (i + 2) * BKC);

        const uint32_t st = sbase + (i % NSTG) * STAGE;
        #pragma unroll
        for (int ks = 0; ks < 4; ks++) {
            uint32_t a_[4][4];
            #pragma unroll
            for (int fm = 0; fm < 4; fm++) {
                int row = wm * 64 + fm * 16 + a_r;
                uint32_t so = sw128((uint32_t)(row * 128) + ks * 32 + a_k);
                ldmx4(a_[fm], st + so);
            }
            uint32_t b_[2][4];
            #pragma unroll
            for (int g = 0; g < 2; g++) {
                int row = wn * 32 + g * 16 + b_r;
                uint32_t so = sw128((uint32_t)(row * 128) + ks * 32 + b_k);
                ldmx4(b_[g], st + OFF_B + so);
            }
            #pragma unroll
            for (int fm = 0; fm < 4; fm++)
                #pragma unroll
                for (int fn = 0; fn < 4; fn++)
                    mma16816(c[fm][fn], a_[fm], &b_[fn >> 1][(fn & 1) * 2]);
        }
    }

    // ---- epilogue -------------------------------------------------------
    float rsum[8];
    if (OUTMODE == 3) {
        #pragma unroll
        for (int r = 0; r < 8; r++) rsum[r] = 0.f;
    }

    #pragma unroll
    for (int fm = 0; fm < 4; fm++) {
        int rowb = row0 + wm * 64 + fm * 16 + (lane >> 2);
        float rs0 = 0.f, rs1 = 0.f;
        if (BIASMODE == 2) { rs0 = bp[rowb]; rs1 = bp[rowb + 8]; }
        if (BIASMODE == 4) {
            const float* p0 = bp + (size_t)rowb * 16;
            const float* p1 = bp + (size_t)(rowb + 8) * 16;
            float s0 = 0.f, s1 = 0.f;
            #pragma unroll
            for (int j = 0; j < 16; j += 4) {
                s0 += (p0[j] + p0[j+1]) + (p0[j+2] + p0[j+3]);
                s1 += (p1[j] + p1[j+1]) + (p1[j+2] + p1[j+3]);
            }
            rs0 = 1.f / s0; rs1 = 1.f / s1;
        }
        #pragma unroll
        for (int fn = 0; fn < 4; fn++) {
            int col = col0 + wn * 32 + fn * 8 + (lane & 3) * 2;
            float v0 = c[fm][fn][0] * alpha, v1 = c[fm][fn][1] * alpha;
            float v2 = c[fm][fn][2] * alpha, v3 = c[fm][fn][3] * alpha;
            if (BIASMODE == 1) {
                float b0 = bp[col], b1 = bp[col + 1];
                v0 += b0; v1 += b1; v2 += b0; v3 += b1;
            }
            if (BIASMODE == 2) {
                v0 += rs0; v1 += rs0; v2 += rs1; v3 += rs1;
            }
            if (BIASMODE == 4) {
                v0 *= rs0; v1 *= rs0; v2 *= rs1; v3 *= rs1;
            }
            size_t o0 = zC + (size_t)rowb * N + col;
            size_t o1 = o0 + (size_t)8 * N;
            if (OUTMODE == 0) {
                *(float2*)(Cf + o0) = make_float2(v0, v1);
                *(float2*)(Cf + o1) = make_float2(v2, v3);
            } else if (OUTMODE == 2) {
                *(uint32_t*)(Chi + o0) = hpack(v0, v1);
                *(uint32_t*)(Chi + o1) = hpack(v2, v3);
            } else {                                  // OUTMODE == 3
                float e0 = ex2(v0), e1 = ex2(v1);
                float e2 = ex2(v2), e3 = ex2(v3);
                *(uint32_t*)(Chi + o0) = hpack(e0, e1);
                *(uint32_t*)(Chi + o1) = hpack(e2, e3);
                rsum[fm * 2]     += e0 + e1;
                rsum[fm * 2 + 1] += e2 + e3;
            }
        }
    }

    if (OUTMODE == 3) {
        // deterministic row-sum reduction -> per-CTA partials
        #pragma unroll
        for (int r = 0; r < 8; r++) {
            rsum[r] += __shfl_xor_sync(0xffffffffu, rsum[r], 1);
            rsum[r] += __shfl_xor_sync(0xffffffffu, rsum[r], 2);
        }
        __syncthreads();                      // safe to reuse stage smem
        float* arr = (float*)smem;            // [4][128]
        if ((lane & 3) == 0) {
            #pragma unroll
            for (int fm = 0; fm < 4; fm++) {
                int r0 = wm * 64 + fm * 16 + (lane >> 2);
                arr[wn * 128 + r0]     = rsum[fm * 2];
                arr[wn * 128 + r0 + 8] = rsum[fm * 2 + 1];
            }
        }
        __syncthreads();
        if (tid < 128) {
            float s = (arr[tid] + arr[128 + tid]) + (arr[256 + tid] + arr[384 + tid]);
            size_t grow = (size_t)blockIdx.z * (gridDim.y * BM) + row0 + tid;
            Cf[grow * gridDim.x + blockIdx.x] = s;
        }
    }
}

// ---------------------------------------------------------------------------
// Merged convert: 4 segments fp32->fp16; the KEY segment also computes
// cs[row] = dot(fp16(key_row), w16) * log2e/32 (2 rows per CTA, deterministic).
// ---------------------------------------------------------------------------
__global__ void __launch_bounds__(256) cvt4_kernel(
    const float* __restrict__ s0, __half* __restrict__ d0, unsigned B0,
    const float* __restrict__ s1, __half* __restrict__ d1, unsigned B1,
    const float* __restrict__ s2, __half* __restrict__ d2, unsigned B2,
    const float* __restrict__ s3, __half* __restrict__ d3,
    const __half* __restrict__ w16, float* __restrict__ cs)
{
    unsigned b = blockIdx.x;
    const float* s; __half* d;
    bool iskey = false;
    unsigned kb = 0;
    if (b < B0)                { s = s0; d = d0; }
    else if (b < B0 + B1)      { s = s1; d = d1; b -= B0; iskey = true; kb = b; }
    else if (b < B0 + B1 + B2) { s = s2; d = d2; b -= B0 + B1; }
    else                       { s = s3; d = d3; b -= B0 + B1 + B2; }
    const int tid = threadIdx.x;
    size_t i = ((size_t)b * 256 + tid) * 8;
    float4 v0 = *(const float4*)(s + i);
    float4 v1 = *(const float4*)(s + i + 4);
    uint4 o;
    o.x = hpack(v0.x, v0.y);
    o.y = hpack(v0.z, v0.w);
    o.z = hpack(v1.x, v1.y);
    o.w = hpack(v1.z, v1.w);
    *(uint4*)(d + i) = o;

    if (iskey) {
        // rows 2*kb (threads 0-127) and 2*kb+1 (threads 128-255);
        // thread handles row elements (tid&127)*8..+7 -> w16 uint4 idx (tid&127)
        const uint4* wr = (const uint4*)w16;
        uint4 u = wr[tid & 127];
        float2 a0 = __half22float2(*(__half2*)&o.x), b0 = __half22float2(*(__half2*)&u.x);
        float2 a1 = __half22float2(*(__half2*)&o.y), b1 = __half22float2(*(__half2*)&u.y);
        float2 a2 = __half22float2(*(__half2*)&o.z), b2 = __half22float2(*(__half2*)&u.z);
        float2 a3 = __half22float2(*(__half2*)&o.w), b3 = __half22float2(*(__half2*)&u.w);
        float sdot = a0.x * b0.x + a0.y * b0.y + a1.x * b1.x + a1.y * b1.y
                   + a2.x * b2.x + a2.y * b2.y + a3.x * b3.x + a3.y * b3.y;
        #pragma unroll
        for (int off = 16; off; off >>= 1)
            sdot += __shfl_xor_sync(0xffffffffu, sdot, off);
        __shared__ float red[8];
        if ((tid & 31) == 0) red[tid >> 5] = sdot;
        __syncthreads();
        if ((tid & 127) == 0) {
            int h = tid >> 7;
            float t = (red[h*4] + red[h*4+1]) + (red[h*4+2] + red[h*4+3]);
            cs[(size_t)kb * 2 + h] = t * (0.03125f * LOG2E);
        }
    }
}

// ---------------------------------------------------------------------------
// Transposed convert: W [K,N] fp32 -> Wt [N,K] fp16   (Wv only)
// ---------------------------------------------------------------------------
__global__ void transpose_cvt_kernel(const float* __restrict__ W,
                                     __half* __restrict__ hi, int K, int N)
{
    __shared__ float t[32][33];
    int n0 = blockIdx.x * 32, k0 = blockIdx.y * 32;
    int x = threadIdx.x, y = threadIdx.y;
    #pragma unroll
    for (int j = 0; j < 32; j += 8)
        t[y + j][x] = W[(size_t)(k0 + y + j) * N + n0 + x];
    __syncthreads();
    #pragma unroll
    for (int j = 0; j < 32; j += 8)
        hi[(size_t)(n0 + y + j) * K + k0 + x] = __float2half_rn(t[x][y + j]);
}

// ---------------------------------------------------------------------------
// w16 = fp16(Wk @ bq)  (dot in fp32, stored fp16).  One block per row.
// ---------------------------------------------------------------------------
__global__ void __launch_bounds__(256) wvec_kernel(
    const float* __restrict__ Wk, const float* __restrict__ bq,
    __half* __restrict__ w16)
{
    const int i = blockIdx.x;
    const int tid = threadIdx.x;
    float s = 0.f;
    #pragma unroll
    for (int j = 0; j < 4; j++) {
        int o = tid + j * 256;
        s += Wk[(size_t)i * SDK + o] * bq[o];
    }
    #pragma unroll
    for (int off = 16; off; off >>= 1)
        s += __shfl_xor_sync(0xffffffffu, s, off);
    __shared__ float red[8];
    if ((tid & 31) == 0) red[tid >> 5] = s;
    __syncthreads();
    if (tid == 0) {
        float t = 0.f;
        #pragma unroll
        for (int k = 0; k < 8; k++) t += red[k];
        w16[i] = __float2half_rn(t);
    }
}

// ---------------------------------------------------------------------------
// M2 split-K reduce: M2[i] = fp16(sum of 4 fp32 partials)
// ---------------------------------------------------------------------------
__global__ void __launch_bounds__(256) m2red_kernel(
    const float* __restrict__ p, __half* __restrict__ out)
{
    const size_t S = (size_t)SDQ * SDK;
    size_t i = (size_t)blockIdx.x * 256 + threadIdx.x;
    float s = (p[i] + p[i + S]) + (p[i + 2 * S] + p[i + 3 * S]);
    out[i] = __float2half_rn(s);
}

// ---------------------------------------------------------------------------
// kernel_launch
// ---------------------------------------------------------------------------
extern "C" void kernel_launch(void* const* d_in, const int* in_sizes, int n_in,
                              void* d_out, int out_size)
{
    const float* query = (const float*)d_in[0];
    const float* key   = (const float*)d_in[1];
    const float* Wq    = (const float*)d_in[2];
    const float* bq    = (const float*)d_in[3];
    const float* Wk    = (const float*)d_in[4];
    const float* bk    = (const float*)d_in[5];   // vanishes under softmax
    const float* Wv    = (const float*)d_in[6];
    const float* bv    = (const float*)d_in[7];
    float* out = (float*)d_out;
    (void)bk;

    __half *qh,*kh,*wq16,*wk16,*wvt,*M2,*Kred,*Vth,*Sf,*w16;
    float *cs,*part,*m2p;
    cudaGetSymbolAddress((void**)&qh,   g_qh);
    cudaGetSymbolAddress((void**)&kh,   g_kh);
    cudaGetSymbolAddress((void**)&wq16, g_wq16);
    cudaGetSymbolAddress((void**)&wk16, g_wk16);
    cudaGetSymbolAddress((void**)&wvt,  g_wvt);
    cudaGetSymbolAddress((void**)&M2,   g_M2);
    cudaGetSymbolAddress((void**)&Kred, g_Kred);
    cudaGetSymbolAddress((void**)&Vth,  g_Vth);
    cudaGetSymbolAddress((void**)&Sf,   g_Sf);
    cudaGetSymbolAddress((void**)&w16,  g_w16);
    cudaGetSymbolAddress((void**)&cs,   g_cs);
    cudaGetSymbolAddress((void**)&part, g_part);
    cudaGetSymbolAddress((void**)&m2p,  g_m2p);

    cudaFuncSetAttribute(mma_gemm<0,0>, cudaFuncAttributeMaxDynamicSharedMemorySize, GEMM_SMEM);
    cudaFuncSetAttribute(mma_gemm<2,0>, cudaFuncAttributeMaxDynamicSharedMemorySize, GEMM_SMEM);
    cudaFuncSetAttribute(mma_gemm<2,2>, cudaFuncAttributeMaxDynamicSharedMemorySize, GEMM_SMEM);
    cudaFuncSetAttribute(mma_gemm<3,1>, cudaFuncAttributeMaxDynamicSharedMemorySize, GEMM_SMEM);
    cudaFuncSetAttribute(mma_gemm<0,4>, cudaFuncAttributeMaxDynamicSharedMemorySize, GEMM_SMEM);

    // 1. w16 = fp16(Wk @ bq)
    wvec_kernel<<<SDK, 256>>>(Wk, bq, w16);

    // 2. all fp32->fp16 converts in ONE launch; key segment also emits cs
    {
        const unsigned Bq  = (unsigned)((size_t)NB * SLQ * SDQ / 2048);  // 12288
        const unsigned Bk  = (unsigned)((size_t)NB * SLK * SDK / 2048);  // 16384
        const unsigned Bwq = (unsigned)((size_t)SDQ * SDK / 2048);       // 384
        const unsigned Bwk = (unsigned)((size_t)SDK * SDK / 2048);       // 512
        cvt4_kernel<<<Bq + Bk + Bwq + Bwk, 256>>>(
            query, qh, Bq, key, kh, Bk, Wq, wq16, Bwq, Wk, wk16, w16, cs);
    }
    transpose_cvt_kernel<<<dim3(SDK/32, SDK/32), dim3(32,8)>>>(Wv, wvt, SDK, SDK);

    // 3. M2 = Wq @ Wk^T  (M=768, N=1024, K=1024) — split-K x4 (fp32 partials)
    mma_gemm<0,0><<<dim3(SDK/BN, SDQ/BM, 4), 256, GEMM_SMEM>>>(
        wq16, wk16, nullptr, m2p, nullptr,
        SDK, SDK, /*Kloop=*/256, 1.f,
        256, 256, (long)SDQ*SDK, 0);
    m2red_kernel<<<(SDQ*SDK)/256, 256>>>(m2p, M2);

    // 4. Kred = key @ M2^T  (M=32768, N=768, K=1024) -> fp16
    mma_gemm<2,0><<<dim3(SDQ/BN, (NB*SLK)/BM, 1), 256, GEMM_SMEM>>>(
        kh, M2, nullptr, nullptr, Kred, SDQ, SDK, SDK, 1.f, 0, 0, 0, 0);

    // 5. V projection, transposed out: Vt[b][d][t] (M=1024, N=2048, K=1024)
    mma_gemm<2,2><<<dim3(SLK/BN, SDK/BM, NB), 256, GEMM_SMEM>>>(
        wvt, kh, bv, nullptr, Vth,
        SLK, SDK, SDK, 1.f, 0, (long)SLK*SDK, (long)SDK*SLK, 0);

    // 6. Sf = exp2(query @ Kred^T * log2e/32 + cs), plus deterministic
    //    per-CTA row-sum partials (gridDim.x = 16 per row)
    mma_gemm<3,1><<<dim3(SLK/BN, SLQ/BM, NB), 256, GEMM_SMEM>>>(
        qh, Kred, cs, part, Sf,
        SLK, SDQ, SDQ, 0.03125f * LOG2E,
        (long)SLQ*SDQ, (long)SLK*SDQ, (long)SLQ*SLK, SLK);

    // 7. out = (Sf @ Vt^T) * (1/rowsum from 16 partials)  (M=2048, N=1024)
    mma_gemm<0,4><<<dim3(SDK/BN, SLQ/BM, NB), 256, GEMM_SMEM>>>(
        Sf, Vth, part, out, nullptr,
        SDK, SLK, SLK, 1.f,
        (long)SLQ*SLK, (long)SDK*SLK, (long)SLQ*SDK, (long)SLQ*16);
}